// round 3
// baseline (speedup 1.0000x reference)
#include <cuda_runtime.h>
#include <math.h>

#define EMAX 320000
#define NMAX 10000
#define HS   (1<<20)
#define INIT_LIMIT ((long long)(NMAX)*128 > (long long)HS ? (long long)(NMAX)*128 : (long long)HS)

// ---------------- scratch (static device arrays; no allocation) ----------------
__device__ long long g_hkey[HS];
__device__ int       g_hval[HS];
__device__ float g_gates[EMAX];
__device__ int   g_rev[EMAX];
__device__ float g_PP[(long long)EMAX*768];   // edge_feature @ [We1_b | We1_c]
__device__ float g_XX[NMAX*768];              // x @ [We1_a | We1_d]
__device__ float g_h1[(long long)EMAX*384];
__device__ float g_etmp[(long long)EMAX*128];
__device__ float g_pe[(long long)EMAX*128];
__device__ float g_qx[NMAX*128];
__device__ float g_vx[NMAX*128];
__device__ float g_seg[NMAX*128];
__device__ float g_subj[NMAX*128];
__device__ float g_obj[NMAX*128];
__device__ float g_cnts[NMAX];
__device__ float g_cntd[NMAX];
__device__ float g_twin_in[NMAX*256];
__device__ float g_twin[NMAX*128];
__device__ float g_xcat[NMAX*256];
__device__ float g_ph[NMAX*256];
__device__ float g_ptmp[NMAX*128];
__device__ float g_BpE[128*768];
__device__ float g_BpN[128*768];

// ---------------- helpers ----------------
__device__ __forceinline__ unsigned hash64(long long k){
    unsigned long long z = (unsigned long long)k;
    z *= 0x9E3779B97F4A7C15ull;
    z ^= z >> 29; z *= 0xBF58476D1CE4E5B9ull; z ^= z >> 32;
    return (unsigned)z;
}

__device__ __forceinline__ void atomicMaxF(float* addr, float v){
    if (v >= 0.f) atomicMax((int*)addr, __float_as_int(v));
    else          atomicMin((unsigned int*)addr, __float_as_uint(v));
}

// ---------------- init (covers BOTH hash table and N*128 node buffers) ----------------
__global__ void init_kernel(int N){
    long long stride = (long long)gridDim.x * blockDim.x;
    long long limit = INIT_LIMIT;
    for (long long i = (long long)blockIdx.x*blockDim.x + threadIdx.x; i < limit; i += stride){
        if (i < HS){
            g_hkey[i] = -1LL;
            g_hval[i] = 0x7fffffff;
        }
        if (i < (long long)N*128){
            g_seg[i]  = __int_as_float(0xff800000); // -inf
            g_subj[i] = 0.f;
            g_obj[i]  = 0.f;
        }
        if (i < N){ g_cnts[i] = 0.f; g_cntd[i] = 0.f; }
    }
}

// ---------------- repack We1 into two [128,768] B matrices ----------------
__global__ void repack_We1(const float* __restrict__ We1){
    int i = blockIdx.x*blockDim.x + threadIdx.x;
    if (i >= 128*768) return;
    int k = i / 768, j = i % 768;
    // edge side: rows 128..255 (edge_feature term), rows 256..383 (rev term)
    g_BpE[i] = (j < 384) ? We1[(128+k)*384 + j] : We1[(256+k)*384 + (j-384)];
    // node side: rows 0..127 (x_i term), rows 384..511 (x_j term)
    g_BpN[i] = (j < 384) ? We1[k*384 + j]       : We1[(384+k)*384 + (j-384)];
}

// ---------------- hash insert (+ degree counts) ----------------
__global__ void hash_insert(const int* __restrict__ src, const int* __restrict__ dst,
                            int E, int N){
    int e = blockIdx.x*blockDim.x + threadIdx.x;
    if (e >= E) return;
    int s = src[e], d = dst[e];
    long long key = (long long)s * N + d;
    unsigned slot = hash64(key) & (HS-1);
    for (;;){
        unsigned long long prev = atomicCAS((unsigned long long*)&g_hkey[slot],
                                            0xFFFFFFFFFFFFFFFFull,
                                            (unsigned long long)key);
        if (prev == 0xFFFFFFFFFFFFFFFFull || (long long)prev == key){
            atomicMin(&g_hval[slot], e);
            break;
        }
        slot = (slot + 1) & (HS-1);
    }
    atomicAdd(&g_cnts[s], 1.f);
    atomicAdd(&g_cntd[d], 1.f);
}

// ---------------- reverse-edge lookup ----------------
__global__ void rev_lookup(const int* __restrict__ src, const int* __restrict__ dst,
                           int E, int N){
    int e = blockIdx.x*blockDim.x + threadIdx.x;
    if (e >= E) return;
    long long rkey = (long long)dst[e] * N + src[e];
    unsigned slot = hash64(rkey) & (HS-1);
    int r = -1;
    for (;;){
        long long k = g_hkey[slot];
        if (k == -1LL) break;
        if (k == rkey){ r = g_hval[slot]; break; }
        slot = (slot + 1) & (HS-1);
    }
    g_rev[e] = r;
}

// ---------------- edge gate MLP (128->64 relu -> 1 sigmoid) ----------------
__global__ __launch_bounds__(256) void gate_kernel(
        const float* __restrict__ ef, const float* __restrict__ Wg1,
        const float* __restrict__ bg1, const float* __restrict__ Wg2,
        const float* __restrict__ bg2, int E){
    __shared__ float sW[128*64];
    __shared__ float sef[4][128];
    __shared__ float sred[4][2];
    __shared__ float sb1[64], sW2[64];
    int t = threadIdx.x;
    for (int i = t; i < 128*64; i += 256) sW[i] = Wg1[i];
    if (t < 64){ sb1[t] = bg1[t]; sW2[t] = Wg2[t]; }
    __syncthreads();
    long long base = (long long)blockIdx.x * 64;
    for (int g0 = 0; g0 < 64; g0 += 4){
        #pragma unroll
        for (int r = 0; r < 2; r++){
            int idx = t + r*256;
            int row = idx >> 7, col = idx & 127;
            long long e = base + g0 + row;
            sef[row][col] = (e < E) ? ef[e*128 + col] : 0.f;
        }
        __syncthreads();
        int lrow = t >> 6;        // 0..3
        int j    = t & 63;        // 0..63
        float acc = sb1[j];
        #pragma unroll 16
        for (int k = 0; k < 128; k++) acc += sef[lrow][k] * sW[k*64 + j];
        float p = fmaxf(acc, 0.f) * sW2[j];
        #pragma unroll
        for (int off = 16; off; off >>= 1) p += __shfl_xor_sync(0xffffffffu, p, off);
        if ((t & 31) == 0) sred[lrow][(t >> 5) & 1] = p;
        __syncthreads();
        if ((t & 63) == 0){
            long long e = base + g0 + lrow;
            if (e < E){
                float tot = sred[lrow][0] + sred[lrow][1] + bg2[0];
                g_gates[e] = 1.f / (1.f + __expf(-tot));
            }
        }
        __syncthreads();
    }
}

// ---------------- generic tiled SGEMM: C = act(A[MxK] @ B[KxNw] + bias) ----------------
__global__ __launch_bounds__(256) void sgemm128(
        const float* __restrict__ A, const float* __restrict__ B,
        const float* __restrict__ bias, float* __restrict__ C,
        int M, int Nw, int K, int relu){
    __shared__ float As[8][128];
    __shared__ float Bs[8][128];
    int tid = threadIdx.x;
    int bm = blockIdx.y, bn = blockIdx.x;

    int rowA = tid >> 1;
    int colA = (tid & 1) << 2;
    int rowB = tid >> 5;
    int colB = (tid & 31) << 2;
    int gRowA = bm*128 + rowA;
    int arow_ok = gRowA < M;

    const float* Ab = A + (size_t)gRowA * K + colA;
    const float* Bb = B + (size_t)rowB * Nw + bn*128 + colB;

    float acc[8][8];
    #pragma unroll
    for (int i=0;i<8;i++)
        #pragma unroll
        for (int j=0;j<8;j++) acc[i][j] = 0.f;

    int tr = (tid >> 4) << 3;
    int tc = (tid & 15) << 3;

    for (int k0 = 0; k0 < K; k0 += 8){
        float4 av = arow_ok ? *(const float4*)Ab : make_float4(0,0,0,0);
        float4 bv = *(const float4*)Bb;
        As[colA+0][rowA] = av.x; As[colA+1][rowA] = av.y;
        As[colA+2][rowA] = av.z; As[colA+3][rowA] = av.w;
        *(float4*)&Bs[rowB][colB] = bv;
        __syncthreads();
        #pragma unroll
        for (int k = 0; k < 8; k++){
            float4 a0 = *(const float4*)&As[k][tr];
            float4 a1 = *(const float4*)&As[k][tr+4];
            float4 b0 = *(const float4*)&Bs[k][tc];
            float4 b1 = *(const float4*)&Bs[k][tc+4];
            float ar[8] = {a0.x,a0.y,a0.z,a0.w,a1.x,a1.y,a1.z,a1.w};
            float br[8] = {b0.x,b0.y,b0.z,b0.w,b1.x,b1.y,b1.z,b1.w};
            #pragma unroll
            for (int i=0;i<8;i++)
                #pragma unroll
                for (int j=0;j<8;j++) acc[i][j] += ar[i]*br[j];
        }
        __syncthreads();
        Ab += 8;
        Bb += (size_t)8 * Nw;
    }

    #pragma unroll
    for (int i = 0; i < 8; i++){
        int row = bm*128 + tr + i;
        if (row >= M) break;
        #pragma unroll
        for (int j = 0; j < 8; j += 4){
            int col = bn*128 + tc + j;
            float4 o;
            float b0 = bias ? bias[col+0] : 0.f;
            float b1 = bias ? bias[col+1] : 0.f;
            float b2 = bias ? bias[col+2] : 0.f;
            float b3 = bias ? bias[col+3] : 0.f;
            o.x = acc[i][j+0] + b0;
            o.y = acc[i][j+1] + b1;
            o.z = acc[i][j+2] + b2;
            o.w = acc[i][j+3] + b3;
            if (relu){
                o.x = fmaxf(o.x,0.f); o.y = fmaxf(o.y,0.f);
                o.z = fmaxf(o.z,0.f); o.w = fmaxf(o.w,0.f);
            }
            *(float4*)&C[(size_t)row*Nw + col] = o;
        }
    }
}

// ---------------- combine gathered pieces -> h1 = relu(...) ----------------
__global__ __launch_bounds__(128) void build_h1(
        const int* __restrict__ src, const int* __restrict__ dst,
        const float* __restrict__ be1, int E){
    long long e = blockIdx.x;
    int t = threadIdx.x;
    int s = src[e], d = dst[e], rv = g_rev[e];
    float g = g_gates[e];
    const float* xs = g_XX + (size_t)s*768;
    const float* xd = g_XX + (size_t)d*768 + 384;
    const float* pp = g_PP + (size_t)e*768;
    const float* pr = (rv >= 0) ? (g_PP + (size_t)rv*768 + 384) : 0;
    #pragma unroll
    for (int r = 0; r < 3; r++){
        int j = t + r*128;
        float v = be1[j] + xs[j] + pp[j] + xd[j];
        if (rv >= 0) v += g * pr[j];
        g_h1[e*384 + j] = fmaxf(v, 0.f);
    }
}

// ---------------- LayerNorm over edge rows + subj/obj segment sums ----------------
__global__ __launch_bounds__(256) void ln_edge(
        const float* __restrict__ ge, const float* __restrict__ be,
        const int* __restrict__ src, const int* __restrict__ dst,
        float* __restrict__ out_edge, int E){
    long long e = (long long)blockIdx.x * 8 + (threadIdx.x >> 5);
    if (e >= E) return;
    int lane = threadIdx.x & 31;
    const float* row = g_etmp + e*128;
    float4 v = *(const float4*)&row[lane*4];
    float s  = v.x + v.y + v.z + v.w;
    float ss = v.x*v.x + v.y*v.y + v.z*v.z + v.w*v.w;
    #pragma unroll
    for (int off = 16; off; off >>= 1){
        s  += __shfl_xor_sync(0xffffffffu, s,  off);
        ss += __shfl_xor_sync(0xffffffffu, ss, off);
    }
    float mean = s * (1.f/128.f);
    float var  = ss * (1.f/128.f) - mean*mean;
    float rstd = rsqrtf(var + 1e-5f);
    int sN = src[e], dN = dst[e];
    float vv[4] = {v.x, v.y, v.z, v.w};
    #pragma unroll
    for (int q = 0; q < 4; q++){
        int c = lane*4 + q;
        float val = (vv[q] - mean) * rstd * ge[c] + be[c];
        out_edge[e*128 + c] = val;
        atomicAdd(&g_subj[(size_t)sN*128 + c], val);
        atomicAdd(&g_obj [(size_t)dN*128 + c], val);
    }
}

// ---------------- per-edge attention MLP + softmax + scatter-max ----------------
__global__ __launch_bounds__(128) void attention_kernel(
        const int* __restrict__ src, const int* __restrict__ dst,
        const float* __restrict__ A1, const float* __restrict__ a1,
        const float* __restrict__ A2, const float* __restrict__ a2,
        int E){
    __shared__ float sA1t[64*64];   // [c][o]
    __shared__ float sA2t[64*32];   // [c][o]
    __shared__ float sa1[64], sa2[32];
    __shared__ float q_s[128], e_s[128], v_s[128], h2_s[256];
    int t = threadIdx.x;
    for (int i = t; i < 4096; i += 128){ int o = i >> 6, c = i & 63; sA1t[c*64 + o] = A1[i]; }
    for (int i = t; i < 2048; i += 128){ int o = i >> 6, c = i & 63; sA2t[c*32 + o] = A2[i]; }
    if (t < 64) sa1[t] = a1[t];
    if (t < 32) sa2[t] = a2[t];
    __syncthreads();

    for (long long e = blockIdx.x; e < E; e += gridDim.x){
        int s = src[e], d = dst[e];
        q_s[t] = g_qx[(size_t)s*128 + t];
        e_s[t] = g_pe[e*128 + t];
        v_s[t] = g_vx[(size_t)d*128 + t];
        __syncthreads();

        float o1[2];
        #pragma unroll
        for (int r = 0; r < 2; r++){
            int idx = t + r*128;
            int o = idx >> 2, hh = idx & 3;
            float acc = sa1[o];
            #pragma unroll 8
            for (int c = 0; c < 32; c++) acc += q_s[c*4 + hh] * sA1t[c*64 + o];
            #pragma unroll 8
            for (int c = 0; c < 32; c++) acc += e_s[c*4 + hh] * sA1t[(32+c)*64 + o];
            o1[r] = fmaxf(acc, 0.f);
        }
        h2_s[t] = o1[0];
        h2_s[t + 128] = o1[1];
        __syncthreads();

        int hh = t >> 5;     // warp id == head
        int o  = t & 31;
        float acc = sa2[o];
        #pragma unroll 16
        for (int c = 0; c < 64; c++) acc += h2_s[(c << 2) + hh] * sA2t[c*32 + o];

        float m = acc;
        #pragma unroll
        for (int off = 16; off; off >>= 1) m = fmaxf(m, __shfl_xor_sync(0xffffffffu, m, off));
        float ex = __expf(acc - m);
        float ssum = ex;
        #pragma unroll
        for (int off = 16; off; off >>= 1) ssum += __shfl_xor_sync(0xffffffffu, ssum, off);
        float prob = ex / ssum;

        int flat = (o << 2) + hh;
        float val = prob * v_s[flat];
        atomicMaxF(&g_seg[(size_t)s*128 + flat], val);
        __syncthreads();
    }
}

// ---------------- node-side glue ----------------
__global__ void build_twin_in(int N){
    int i = blockIdx.x*blockDim.x + threadIdx.x;
    if (i >= N*128) return;
    int n = i >> 7, c = i & 127;
    g_twin_in[(size_t)n*256 + c]       = g_subj[i] / fmaxf(g_cnts[n], 1.f);
    g_twin_in[(size_t)n*256 + 128 + c] = g_obj[i]  / fmaxf(g_cntd[n], 1.f);
}

__global__ void build_xcat(const float* __restrict__ x, int N){
    int i = blockIdx.x*blockDim.x + threadIdx.x;
    if (i >= N*128) return;
    int n = i >> 7, c = i & 127;
    g_xcat[(size_t)n*256 + c] = x[i];
    float s = (g_cnts[n] > 0.f) ? g_seg[i] : 0.f;
    s = fmaxf(s, 0.f);
    float tw = g_twin[i];
    g_xcat[(size_t)n*256 + 128 + c] = s * (1.f / (1.f + __expf(-tw)));
}

// ---------------- final LayerNorm ----------------
__global__ __launch_bounds__(256) void ln_final(
        const float* __restrict__ gn, const float* __restrict__ bn,
        float* __restrict__ out_x, int N){
    int n = blockIdx.x * 8 + (threadIdx.x >> 5);
    if (n >= N) return;
    int lane = threadIdx.x & 31;
    const float* row = g_ptmp + (size_t)n*128;
    float4 v = *(const float4*)&row[lane*4];
    float s  = v.x + v.y + v.z + v.w;
    float ss = v.x*v.x + v.y*v.y + v.z*v.z + v.w*v.w;
    #pragma unroll
    for (int off = 16; off; off >>= 1){
        s  += __shfl_xor_sync(0xffffffffu, s,  off);
        ss += __shfl_xor_sync(0xffffffffu, ss, off);
    }
    float mean = s * (1.f/128.f);
    float var  = ss * (1.f/128.f) - mean*mean;
    float rstd = rsqrtf(var + 1e-5f);
    float vv[4] = {v.x, v.y, v.z, v.w};
    #pragma unroll
    for (int q = 0; q < 4; q++){
        int c = lane*4 + q;
        out_x[(size_t)n*128 + c] = (vv[q] - mean) * rstd * gn[c] + bn[c];
    }
}

// ---------------- host ----------------
extern "C" void kernel_launch(void* const* d_in, const int* in_sizes, int n_in,
                              void* d_out, int out_size){
    const float* x    = (const float*)d_in[0];
    const float* ef   = (const float*)d_in[1];
    const int*   eidx = (const int*)  d_in[2];
    const float* Wg1  = (const float*)d_in[3];
    const float* bg1  = (const float*)d_in[4];
    const float* Wg2  = (const float*)d_in[5];
    const float* bg2  = (const float*)d_in[6];
    const float* We1  = (const float*)d_in[7];
    const float* be1  = (const float*)d_in[8];
    const float* We2  = (const float*)d_in[9];
    const float* be2  = (const float*)d_in[10];
    const float* ge   = (const float*)d_in[11];
    const float* beta_e=(const float*)d_in[12];
    const float* Wq   = (const float*)d_in[13];
    const float* bq   = (const float*)d_in[14];
    const float* Wpe  = (const float*)d_in[15];
    const float* bpe  = (const float*)d_in[16];
    const float* Wv   = (const float*)d_in[17];
    const float* bv   = (const float*)d_in[18];
    const float* A1   = (const float*)d_in[19];
    const float* a1   = (const float*)d_in[20];
    const float* A2   = (const float*)d_in[21];
    const float* a2   = (const float*)d_in[22];
    const float* Wt   = (const float*)d_in[23];
    const float* bt   = (const float*)d_in[24];
    const float* Wp1  = (const float*)d_in[25];
    const float* bp1  = (const float*)d_in[26];
    const float* Wp2  = (const float*)d_in[27];
    const float* bp2  = (const float*)d_in[28];
    const float* gn   = (const float*)d_in[29];
    const float* bn   = (const float*)d_in[30];

    int N = in_sizes[0] / 128;
    int E = in_sizes[2] / 2;
    const int* src = eidx;
    const int* dst = eidx + E;

    float* out_x = (float*)d_out;                        // [N,128]
    float* out_e = (float*)d_out + (size_t)N * 128;      // [E,128]

    // symbol addresses for GEMM operands
    float *pPP, *pXX, *pH1, *pETMP, *pPE, *pQX, *pVX;
    float *pTIN, *pTWIN, *pXCAT, *pPH, *pPTMP, *pBpE, *pBpN;
    cudaGetSymbolAddress((void**)&pPP,   g_PP);
    cudaGetSymbolAddress((void**)&pXX,   g_XX);
    cudaGetSymbolAddress((void**)&pH1,   g_h1);
    cudaGetSymbolAddress((void**)&pETMP, g_etmp);
    cudaGetSymbolAddress((void**)&pPE,   g_pe);
    cudaGetSymbolAddress((void**)&pQX,   g_qx);
    cudaGetSymbolAddress((void**)&pVX,   g_vx);
    cudaGetSymbolAddress((void**)&pTIN,  g_twin_in);
    cudaGetSymbolAddress((void**)&pTWIN, g_twin);
    cudaGetSymbolAddress((void**)&pXCAT, g_xcat);
    cudaGetSymbolAddress((void**)&pPH,   g_ph);
    cudaGetSymbolAddress((void**)&pPTMP, g_ptmp);
    cudaGetSymbolAddress((void**)&pBpE,  g_BpE);
    cudaGetSymbolAddress((void**)&pBpN,  g_BpN);

    // 1) init state (MUST cover max(HS, N*128) elements — replay correctness)
    init_kernel<<<2048, 256>>>(N);
    // 2) repack We1
    repack_We1<<<(128*768 + 255)/256, 256>>>(We1);
    // 3) hash insert + degree counts
    hash_insert<<<(E + 255)/256, 256>>>(src, dst, E, N);
    // 4) reverse lookup
    rev_lookup<<<(E + 255)/256, 256>>>(src, dst, E, N);
    // 5) gates
    gate_kernel<<<(E + 63)/64, 256>>>(ef, Wg1, bg1, Wg2, bg2, E);
    // 6) node part of nn_edge layer1: XX = x @ BpN   [N,768]
    { dim3 g(768/128, (N+127)/128); sgemm128<<<g,256>>>(x, pBpN, 0, pXX, N, 768, 128, 0); }
    // 7) edge part: PP = edge_feature @ BpE          [E,768]
    { dim3 g(768/128, (E+127)/128); sgemm128<<<g,256>>>(ef, pBpE, 0, pPP, E, 768, 128, 0); }
    // 8) combine -> h1 = relu(...)
    build_h1<<<E, 128>>>(src, dst, be1, E);
    // 9) etmp = h1 @ We2 + be2
    { dim3 g(128/128, (E+127)/128); sgemm128<<<g,256>>>(pH1, We2, be2, pETMP, E, 128, 384, 0); }
    // 10) LN over edge rows -> out_e, and subj/obj segment sums
    ln_edge<<<(E + 7)/8, 256>>>(ge, beta_e, src, dst, out_e, E);
    // 11) projections
    { dim3 g(1, (N+127)/128); sgemm128<<<g,256>>>(x, Wq, bq, pQX, N, 128, 128, 0); }
    { dim3 g(1, (N+127)/128); sgemm128<<<g,256>>>(x, Wv, bv, pVX, N, 128, 128, 0); }
    { dim3 g(1, (E+127)/128); sgemm128<<<g,256>>>(ef, Wpe, bpe, pPE, E, 128, 128, 0); }
    // 12) attention + scatter-max
    attention_kernel<<<4096, 128>>>(src, dst, A1, a1, A2, a2, E);
    // 13) twin input (segment means)
    build_twin_in<<<(N*128 + 255)/256, 256>>>(N);
    // 14) twin = twin_in @ Wt + bt
    { dim3 g(1, (N+127)/128); sgemm128<<<g,256>>>(pTIN, Wt, bt, pTWIN, N, 128, 256, 0); }
    // 15) xcat = [x, relu(gated seg-max) * sigmoid(twin)]
    build_xcat<<<(N*128 + 255)/256, 256>>>(x, N);
    // 16) ph = relu(xcat @ Wp1 + bp1)
    { dim3 g(256/128, (N+127)/128); sgemm128<<<g,256>>>(pXCAT, Wp1, bp1, pPH, N, 256, 256, 1); }
    // 17) ptmp = ph @ Wp2 + bp2
    { dim3 g(1, (N+127)/128); sgemm128<<<g,256>>>(pPH, Wp2, bp2, pPTMP, N, 128, 256, 0); }
    // 18) final LN -> out_x
    ln_final<<<(N + 7)/8, 256>>>(gn, bn, out_x, N);
}

// round 4
// speedup vs baseline: 1.2126x; 1.2126x over previous
#include <cuda_runtime.h>
#include <math.h>

#define EMAX 320000
#define NMAX 10000
#define HS   (1<<20)
#define PPW  1024   // PP GEMM width: [We1_e 384 | We1_rev 384 | Wpe 128 | Wg1 64 | pad 64]
#define INIT_LIMIT ((long long)(NMAX)*128 > (long long)HS ? (long long)(NMAX)*128 : (long long)HS)

// ---------------- scratch (static device arrays; no allocation) ----------------
__device__ long long g_hkey[HS];
__device__ int       g_hval[HS];
__device__ float g_gates[EMAX];
__device__ int   g_rev[EMAX];
__device__ float g_PP[(long long)EMAX*PPW];
__device__ float g_XX[NMAX*768];
__device__ float g_h1[(long long)EMAX*384];
__device__ float g_etmp[(long long)EMAX*128];
__device__ float g_qx[NMAX*128];
__device__ float g_vx[NMAX*128];
__device__ float g_seg[NMAX*128];
__device__ float g_subj[NMAX*128];
__device__ float g_obj[NMAX*128];
__device__ float g_cnts[NMAX];
__device__ float g_cntd[NMAX];
__device__ float g_twin_in[NMAX*256];
__device__ float g_twin[NMAX*128];
__device__ float g_xcat[NMAX*256];
__device__ float g_ph[NMAX*256];
__device__ float g_ptmp[NMAX*128];
__device__ float g_BpE[128*PPW];
__device__ float g_BpN[128*768];
__device__ float g_biasPP[PPW];

// ---------------- helpers ----------------
__device__ __forceinline__ unsigned hash64(long long k){
    unsigned long long z = (unsigned long long)k;
    z *= 0x9E3779B97F4A7C15ull;
    z ^= z >> 29; z *= 0xBF58476D1CE4E5B9ull; z ^= z >> 32;
    return (unsigned)z;
}

__device__ __forceinline__ void atomicMaxF(float* addr, float v){
    if (v >= 0.f) atomicMax((int*)addr, __float_as_int(v));
    else          atomicMin((unsigned int*)addr, __float_as_uint(v));
}

// ---------------- init ----------------
__global__ void init_kernel(int N){
    long long stride = (long long)gridDim.x * blockDim.x;
    long long limit = INIT_LIMIT;
    for (long long i = (long long)blockIdx.x*blockDim.x + threadIdx.x; i < limit; i += stride){
        if (i < HS){
            g_hkey[i] = -1LL;
            g_hval[i] = 0x7fffffff;
        }
        if (i < (long long)N*128){
            g_seg[i]  = __int_as_float(0xff800000); // -inf
            g_subj[i] = 0.f;
            g_obj[i]  = 0.f;
        }
        if (i < N){ g_cnts[i] = 0.f; g_cntd[i] = 0.f; }
    }
}

// ---------------- repack: B for the big edge GEMM [128, PPW] ----------------
__global__ void repack_We1(const float* __restrict__ We1,
                           const float* __restrict__ Wpe,
                           const float* __restrict__ Wg1){
    int i = blockIdx.x*blockDim.x + threadIdx.x;
    if (i >= 128*PPW) return;
    int k = i / PPW, j = i % PPW;
    float v;
    if      (j < 384)  v = We1[(128+k)*384 + j];          // edge term
    else if (j < 768)  v = We1[(256+k)*384 + (j-384)];    // rev term
    else if (j < 896)  v = Wpe[k*128 + (j-768)];          // pe projection
    else if (j < 960)  v = Wg1[k*64 + (j-896)];           // gate hidden
    else               v = 0.f;                            // pad
    g_BpE[i] = v;
}

__global__ void repack_BpN_bias(const float* __restrict__ We1,
                                const float* __restrict__ bpe,
                                const float* __restrict__ bg1){
    int i = blockIdx.x*blockDim.x + threadIdx.x;
    if (i < 128*768){
        int k = i / 768, j = i % 768;
        g_BpN[i] = (j < 384) ? We1[k*384 + j] : We1[(384+k)*384 + (j-384)];
    }
    if (i < PPW){
        float v = 0.f;
        if      (i >= 768 && i < 896) v = bpe[i-768];
        else if (i >= 896 && i < 960) v = bg1[i-896];
        g_biasPP[i] = v;
    }
}

// ---------------- hash insert (+ degree counts) ----------------
__global__ void hash_insert(const int* __restrict__ src, const int* __restrict__ dst,
                            int E, int N){
    int e = blockIdx.x*blockDim.x + threadIdx.x;
    if (e >= E) return;
    int s = src[e], d = dst[e];
    long long key = (long long)s * N + d;
    unsigned slot = hash64(key) & (HS-1);
    for (;;){
        unsigned long long prev = atomicCAS((unsigned long long*)&g_hkey[slot],
                                            0xFFFFFFFFFFFFFFFFull,
                                            (unsigned long long)key);
        if (prev == 0xFFFFFFFFFFFFFFFFull || (long long)prev == key){
            atomicMin(&g_hval[slot], e);
            break;
        }
        slot = (slot + 1) & (HS-1);
    }
    atomicAdd(&g_cnts[s], 1.f);
    atomicAdd(&g_cntd[d], 1.f);
}

// ---------------- reverse-edge lookup ----------------
__global__ void rev_lookup(const int* __restrict__ src, const int* __restrict__ dst,
                           int E, int N){
    int e = blockIdx.x*blockDim.x + threadIdx.x;
    if (e >= E) return;
    long long rkey = (long long)dst[e] * N + src[e];
    unsigned slot = hash64(rkey) & (HS-1);
    int r = -1;
    for (;;){
        long long k = g_hkey[slot];
        if (k == -1LL) break;
        if (k == rkey){ r = g_hval[slot]; break; }
        slot = (slot + 1) & (HS-1);
    }
    g_rev[e] = r;
}

// ---------------- gate reduce: gates = sigmoid(relu(PP[:,896:960]) @ Wg2 + bg2) ----------------
__global__ __launch_bounds__(256) void gate_reduce(
        const float* __restrict__ Wg2, const float* __restrict__ bg2, int E){
    long long e = (long long)blockIdx.x * 8 + (threadIdx.x >> 5);
    if (e >= E) return;
    int lane = threadIdx.x & 31;
    const float* row = g_PP + e*PPW + 896;
    float2 v = *(const float2*)&row[lane*2];
    float w0 = __ldg(&Wg2[lane*2]);
    float w1 = __ldg(&Wg2[lane*2+1]);
    float p = fmaxf(v.x, 0.f)*w0 + fmaxf(v.y, 0.f)*w1;
    #pragma unroll
    for (int off = 16; off; off >>= 1) p += __shfl_xor_sync(0xffffffffu, p, off);
    if (lane == 0)
        g_gates[e] = 1.f / (1.f + __expf(-(p + bg2[0])));
}

// ---------------- double-buffered tiled SGEMM: C = act(A[MxK] @ B[KxNw] + bias) ----------------
__global__ __launch_bounds__(256) void sgemm128(
        const float* __restrict__ A, const float* __restrict__ B,
        const float* __restrict__ bias, float* __restrict__ C,
        int M, int Nw, int K, int relu){
    __shared__ float As[2][8][128];
    __shared__ float Bs[2][8][128];
    int tid = threadIdx.x;
    int bm = blockIdx.y, bn = blockIdx.x;

    int rowA = tid >> 1;
    int colA = (tid & 1) << 2;
    int rowB = tid >> 5;
    int colB = (tid & 31) << 2;
    int gRowA = bm*128 + rowA;
    int arow_ok = gRowA < M;

    const float* Ab = A + (size_t)gRowA * K + colA;
    const float* Bb = B + (size_t)rowB * Nw + bn*128 + colB;

    float acc[8][8];
    #pragma unroll
    for (int i=0;i<8;i++)
        #pragma unroll
        for (int j=0;j<8;j++) acc[i][j] = 0.f;

    int tr = (tid >> 4) << 3;
    int tc = (tid & 15) << 3;
    int T = K >> 3;

    // preload tile 0
    {
        float4 av = arow_ok ? *(const float4*)Ab : make_float4(0,0,0,0);
        float4 bv = *(const float4*)Bb;
        As[0][colA+0][rowA] = av.x; As[0][colA+1][rowA] = av.y;
        As[0][colA+2][rowA] = av.z; As[0][colA+3][rowA] = av.w;
        *(float4*)&Bs[0][rowB][colB] = bv;
    }
    __syncthreads();

    int p = 0;
    for (int t = 0; t < T; t++){
        float4 av2 = make_float4(0,0,0,0), bv2 = make_float4(0,0,0,0);
        if (t+1 < T){
            if (arow_ok) av2 = *(const float4*)(Ab + (t+1)*8);
            bv2 = *(const float4*)(Bb + (size_t)(t+1)*8*Nw);
        }
        #pragma unroll
        for (int k = 0; k < 8; k++){
            float4 a0 = *(const float4*)&As[p][k][tr];
            float4 a1 = *(const float4*)&As[p][k][tr+4];
            float4 b0 = *(const float4*)&Bs[p][k][tc];
            float4 b1 = *(const float4*)&Bs[p][k][tc+4];
            float ar[8] = {a0.x,a0.y,a0.z,a0.w,a1.x,a1.y,a1.z,a1.w};
            float br[8] = {b0.x,b0.y,b0.z,b0.w,b1.x,b1.y,b1.z,b1.w};
            #pragma unroll
            for (int i=0;i<8;i++)
                #pragma unroll
                for (int j=0;j<8;j++) acc[i][j] += ar[i]*br[j];
        }
        if (t+1 < T){
            int q = p ^ 1;
            As[q][colA+0][rowA] = av2.x; As[q][colA+1][rowA] = av2.y;
            As[q][colA+2][rowA] = av2.z; As[q][colA+3][rowA] = av2.w;
            *(float4*)&Bs[q][rowB][colB] = bv2;
            __syncthreads();
            p = q;
        }
    }

    #pragma unroll
    for (int i = 0; i < 8; i++){
        int row = bm*128 + tr + i;
        if (row >= M) break;
        #pragma unroll
        for (int j = 0; j < 8; j += 4){
            int col = bn*128 + tc + j;
            float4 o;
            float b0 = bias ? bias[col+0] : 0.f;
            float b1 = bias ? bias[col+1] : 0.f;
            float b2 = bias ? bias[col+2] : 0.f;
            float b3 = bias ? bias[col+3] : 0.f;
            o.x = acc[i][j+0] + b0;
            o.y = acc[i][j+1] + b1;
            o.z = acc[i][j+2] + b2;
            o.w = acc[i][j+3] + b3;
            if (relu){
                o.x = fmaxf(o.x,0.f); o.y = fmaxf(o.y,0.f);
                o.z = fmaxf(o.z,0.f); o.w = fmaxf(o.w,0.f);
            }
            *(float4*)&C[(size_t)row*Nw + col] = o;
        }
    }
}

// ---------------- combine gathered pieces -> h1 = relu(...) ----------------
__global__ __launch_bounds__(128) void build_h1(
        const int* __restrict__ src, const int* __restrict__ dst,
        const float* __restrict__ be1, int E){
    long long e = blockIdx.x;
    int t = threadIdx.x;
    int s = src[e], d = dst[e], rv = g_rev[e];
    float g = g_gates[e];
    const float* xs = g_XX + (size_t)s*768;
    const float* xd = g_XX + (size_t)d*768 + 384;
    const float* pp = g_PP + e*PPW;
    const float* pr = (rv >= 0) ? (g_PP + (size_t)rv*PPW + 384) : 0;
    #pragma unroll
    for (int r = 0; r < 3; r++){
        int j = t + r*128;
        float v = be1[j] + xs[j] + pp[j] + xd[j];
        if (rv >= 0) v += g * pr[j];
        g_h1[e*384 + j] = fmaxf(v, 0.f);
    }
}

// ---------------- LayerNorm over edge rows + subj/obj segment sums ----------------
__global__ __launch_bounds__(256) void ln_edge(
        const float* __restrict__ ge, const float* __restrict__ be,
        const int* __restrict__ src, const int* __restrict__ dst,
        float* __restrict__ out_edge, int E){
    long long e = (long long)blockIdx.x * 8 + (threadIdx.x >> 5);
    if (e >= E) return;
    int lane = threadIdx.x & 31;
    const float* row = g_etmp + e*128;
    float4 v = *(const float4*)&row[lane*4];
    float s  = v.x + v.y + v.z + v.w;
    float ss = v.x*v.x + v.y*v.y + v.z*v.z + v.w*v.w;
    #pragma unroll
    for (int off = 16; off; off >>= 1){
        s  += __shfl_xor_sync(0xffffffffu, s,  off);
        ss += __shfl_xor_sync(0xffffffffu, ss, off);
    }
    float mean = s * (1.f/128.f);
    float var  = ss * (1.f/128.f) - mean*mean;
    float rstd = rsqrtf(var + 1e-5f);
    int sN = src[e], dN = dst[e];
    float vv[4] = {v.x, v.y, v.z, v.w};
    #pragma unroll
    for (int q = 0; q < 4; q++){
        int c = lane*4 + q;
        float val = (vv[q] - mean) * rstd * ge[c] + be[c];
        out_edge[e*128 + c] = val;
        atomicAdd(&g_subj[(size_t)sN*128 + c], val);
        atomicAdd(&g_obj [(size_t)dN*128 + c], val);
    }
}

// ---------------- attention: MLP (head-amortized) + softmax + scatter-max ----------------
__global__ __launch_bounds__(256) void attention_kernel(
        const int* __restrict__ src, const int* __restrict__ dst,
        const float* __restrict__ A1, const float* __restrict__ a1,
        const float* __restrict__ A2, const float* __restrict__ a2,
        int E){
    __shared__ float sA1t[64*64];   // [c][o]
    __shared__ float sA2t[64*32];   // [c][o]
    __shared__ float sa1[64], sa2[32];
    __shared__ float qe_s[4][256];  // per slot: [c*4+h], c 0..31 = q, 32..63 = e_proj
    __shared__ float v_s[4][128];
    __shared__ float h1_s[4][256];
    int t = threadIdx.x;
    for (int i = t; i < 4096; i += 256){ int o = i >> 6, c = i & 63; sA1t[c*64 + o] = A1[i]; }
    for (int i = t; i < 2048; i += 256){ int o = i >> 6, c = i & 63; sA2t[c*32 + o] = A2[i]; }
    if (t < 64) sa1[t] = a1[t];
    if (t < 32) sa2[t] = a2[t];
    __syncthreads();

    int slot = t >> 6;   // 0..3
    int o    = t & 63;   // 0..63

    for (long long e0 = (long long)blockIdx.x*4; e0 < E; e0 += (long long)gridDim.x*4){
        long long e = e0 + slot;
        bool ok = (e < E);
        int s = 0, d = 0;
        if (ok){ s = src[e]; d = dst[e]; }
        if (ok){
            if (o < 32){
                ((float4*)qe_s[slot])[o] = ((const float4*)(g_qx + (size_t)s*128))[o];
                ((float4*)v_s[slot])[o]  = ((const float4*)(g_vx + (size_t)d*128))[o];
            } else {
                ((float4*)qe_s[slot])[o] = ((const float4*)(g_PP + e*PPW + 768))[o-32];
            }
        }
        __syncthreads();

        // layer1: out1[o][h] = relu(sum_c in[c][h] * A1t[c][o] + a1[o])
        float b1 = sa1[o];
        float c0 = b1, c1 = b1, c2 = b1, c3 = b1;
        #pragma unroll 8
        for (int c = 0; c < 64; c++){
            float w = sA1t[c*64 + o];
            float4 in = *(const float4*)&qe_s[slot][c*4];
            c0 += w*in.x; c1 += w*in.y; c2 += w*in.z; c3 += w*in.w;
        }
        float4 h1v = make_float4(fmaxf(c0,0.f), fmaxf(c1,0.f), fmaxf(c2,0.f), fmaxf(c3,0.f));
        *(float4*)&h1_s[slot][o*4] = h1v;
        __syncthreads();

        // layer2 + softmax + scatter (first warp of each slot; o = 0..31)
        if (o < 32){
            float b2 = sa2[o];
            float p0 = b2, p1 = b2, p2 = b2, p3 = b2;
            #pragma unroll 8
            for (int c = 0; c < 64; c++){
                float w = sA2t[c*32 + o];
                float4 in = *(const float4*)&h1_s[slot][c*4];
                p0 += w*in.x; p1 += w*in.y; p2 += w*in.z; p3 += w*in.w;
            }
            if (ok){
                float vals[4] = {p0, p1, p2, p3};
                float4 vv = *(const float4*)&v_s[slot][o*4];
                float vvv[4] = {vv.x, vv.y, vv.z, vv.w};
                #pragma unroll
                for (int h = 0; h < 4; h++){
                    float m = vals[h];
                    #pragma unroll
                    for (int off = 16; off; off >>= 1)
                        m = fmaxf(m, __shfl_xor_sync(0xffffffffu, m, off));
                    float ex = __expf(vals[h] - m);
                    float sm = ex;
                    #pragma unroll
                    for (int off = 16; off; off >>= 1)
                        sm += __shfl_xor_sync(0xffffffffu, sm, off);
                    float prob = ex / sm;
                    atomicMaxF(&g_seg[(size_t)s*128 + o*4 + h], prob * vvv[h]);
                }
            }
        }
        __syncthreads();
    }
}

// ---------------- node-side glue ----------------
__global__ void build_twin_in(int N){
    int i = blockIdx.x*blockDim.x + threadIdx.x;
    if (i >= N*128) return;
    int n = i >> 7, c = i & 127;
    g_twin_in[(size_t)n*256 + c]       = g_subj[i] / fmaxf(g_cnts[n], 1.f);
    g_twin_in[(size_t)n*256 + 128 + c] = g_obj[i]  / fmaxf(g_cntd[n], 1.f);
}

__global__ void build_xcat(const float* __restrict__ x, int N){
    int i = blockIdx.x*blockDim.x + threadIdx.x;
    if (i >= N*128) return;
    int n = i >> 7, c = i & 127;
    g_xcat[(size_t)n*256 + c] = x[i];
    float s = (g_cnts[n] > 0.f) ? g_seg[i] : 0.f;
    s = fmaxf(s, 0.f);
    float tw = g_twin[i];
    g_xcat[(size_t)n*256 + 128 + c] = s * (1.f / (1.f + __expf(-tw)));
}

// ---------------- final LayerNorm ----------------
__global__ __launch_bounds__(256) void ln_final(
        const float* __restrict__ gn, const float* __restrict__ bn,
        float* __restrict__ out_x, int N){
    int n = blockIdx.x * 8 + (threadIdx.x >> 5);
    if (n >= N) return;
    int lane = threadIdx.x & 31;
    const float* row = g_ptmp + (size_t)n*128;
    float4 v = *(const float4*)&row[lane*4];
    float s  = v.x + v.y + v.z + v.w;
    float ss = v.x*v.x + v.y*v.y + v.z*v.z + v.w*v.w;
    #pragma unroll
    for (int off = 16; off; off >>= 1){
        s  += __shfl_xor_sync(0xffffffffu, s,  off);
        ss += __shfl_xor_sync(0xffffffffu, ss, off);
    }
    float mean = s * (1.f/128.f);
    float var  = ss * (1.f/128.f) - mean*mean;
    float rstd = rsqrtf(var + 1e-5f);
    float vv[4] = {v.x, v.y, v.z, v.w};
    #pragma unroll
    for (int q = 0; q < 4; q++){
        int c = lane*4 + q;
        out_x[(size_t)n*128 + c] = (vv[q] - mean) * rstd * gn[c] + bn[c];
    }
}

// ---------------- host ----------------
extern "C" void kernel_launch(void* const* d_in, const int* in_sizes, int n_in,
                              void* d_out, int out_size){
    const float* x    = (const float*)d_in[0];
    const float* ef   = (const float*)d_in[1];
    const int*   eidx = (const int*)  d_in[2];
    const float* Wg1  = (const float*)d_in[3];
    const float* bg1  = (const float*)d_in[4];
    const float* Wg2  = (const float*)d_in[5];
    const float* bg2  = (const float*)d_in[6];
    const float* We1  = (const float*)d_in[7];
    const float* be1  = (const float*)d_in[8];
    const float* We2  = (const float*)d_in[9];
    const float* be2  = (const float*)d_in[10];
    const float* ge   = (const float*)d_in[11];
    const float* beta_e=(const float*)d_in[12];
    const float* Wq   = (const float*)d_in[13];
    const float* bq   = (const float*)d_in[14];
    const float* Wpe  = (const float*)d_in[15];
    const float* bpe  = (const float*)d_in[16];
    const float* Wv   = (const float*)d_in[17];
    const float* bv   = (const float*)d_in[18];
    const float* A1   = (const float*)d_in[19];
    const float* a1   = (const float*)d_in[20];
    const float* A2   = (const float*)d_in[21];
    const float* a2   = (const float*)d_in[22];
    const float* Wt   = (const float*)d_in[23];
    const float* bt   = (const float*)d_in[24];
    const float* Wp1  = (const float*)d_in[25];
    const float* bp1  = (const float*)d_in[26];
    const float* Wp2  = (const float*)d_in[27];
    const float* bp2  = (const float*)d_in[28];
    const float* gn   = (const float*)d_in[29];
    const float* bn   = (const float*)d_in[30];

    int N = in_sizes[0] / 128;
    int E = in_sizes[2] / 2;
    const int* src = eidx;
    const int* dst = eidx + E;

    float* out_x = (float*)d_out;                        // [N,128]
    float* out_e = (float*)d_out + (size_t)N * 128;      // [E,128]

    float *pPP, *pXX, *pH1, *pETMP, *pQX, *pVX;
    float *pTIN, *pTWIN, *pXCAT, *pPH, *pPTMP, *pBpE, *pBpN, *pBias;
    cudaGetSymbolAddress((void**)&pPP,   g_PP);
    cudaGetSymbolAddress((void**)&pXX,   g_XX);
    cudaGetSymbolAddress((void**)&pH1,   g_h1);
    cudaGetSymbolAddress((void**)&pETMP, g_etmp);
    cudaGetSymbolAddress((void**)&pQX,   g_qx);
    cudaGetSymbolAddress((void**)&pVX,   g_vx);
    cudaGetSymbolAddress((void**)&pTIN,  g_twin_in);
    cudaGetSymbolAddress((void**)&pTWIN, g_twin);
    cudaGetSymbolAddress((void**)&pXCAT, g_xcat);
    cudaGetSymbolAddress((void**)&pPH,   g_ph);
    cudaGetSymbolAddress((void**)&pPTMP, g_ptmp);
    cudaGetSymbolAddress((void**)&pBpE,  g_BpE);
    cudaGetSymbolAddress((void**)&pBpN,  g_BpN);
    cudaGetSymbolAddress((void**)&pBias, g_biasPP);

    // 1) init state
    init_kernel<<<2048, 256>>>(N);
    // 2) repack weights
    repack_We1<<<(128*PPW + 255)/256, 256>>>(We1, Wpe, Wg1);
    repack_BpN_bias<<<(128*768 + 255)/256, 256>>>(We1, bpe, bg1);
    // 3) hash insert + degree counts
    hash_insert<<<(E + 255)/256, 256>>>(src, dst, E, N);
    // 4) reverse lookup
    rev_lookup<<<(E + 255)/256, 256>>>(src, dst, E, N);
    // 5) node part of nn_edge layer1: XX = x @ BpN   [N,768]
    { dim3 g(768/128, (N+127)/128); sgemm128<<<g,256>>>(x, pBpN, 0, pXX, N, 768, 128, 0); }
    // 6) big edge GEMM: PP = ef @ BpE (+bias)  [E,1024] (edge-term | rev-term | pe | gate-h | pad)
    { dim3 g(PPW/128, (E+127)/128); sgemm128<<<g,256>>>(ef, pBpE, pBias, pPP, E, PPW, 128, 0); }
    // 7) gate sigmoid reduce
    gate_reduce<<<(E + 7)/8, 256>>>(Wg2, bg2, E);
    // 8) combine -> h1 = relu(...)
    build_h1<<<E, 128>>>(src, dst, be1, E);
    // 9) etmp = h1 @ We2 + be2
    { dim3 g(1, (E+127)/128); sgemm128<<<g,256>>>(pH1, We2, be2, pETMP, E, 128, 384, 0); }
    // 10) LN over edge rows -> out_e, and subj/obj segment sums
    ln_edge<<<(E + 7)/8, 256>>>(ge, beta_e, src, dst, out_e, E);
    // 11) q/v projections (node-sized)
    { dim3 g(1, (N+127)/128); sgemm128<<<g,256>>>(x, Wq, bq, pQX, N, 128, 128, 0); }
    { dim3 g(1, (N+127)/128); sgemm128<<<g,256>>>(x, Wv, bv, pVX, N, 128, 128, 0); }
    // 12) attention + scatter-max
    attention_kernel<<<8192, 256>>>(src, dst, A1, a1, A2, a2, E);
    // 13) twin input (segment means)
    build_twin_in<<<(N*128 + 255)/256, 256>>>(N);
    // 14) twin = twin_in @ Wt + bt
    { dim3 g(1, (N+127)/128); sgemm128<<<g,256>>>(pTIN, Wt, bt, pTWIN, N, 128, 256, 0); }
    // 15) xcat = [x, relu(gated seg-max) * sigmoid(twin)]
    build_xcat<<<(N*128 + 255)/256, 256>>>(x, N);
    // 16) ph = relu(xcat @ Wp1 + bp1)
    { dim3 g(256/128, (N+127)/128); sgemm128<<<g,256>>>(pXCAT, Wp1, bp1, pPH, N, 256, 256, 1); }
    // 17) ptmp = ph @ Wp2 + bp2
    { dim3 g(1, (N+127)/128); sgemm128<<<g,256>>>(pPH, Wp2, bp2, pPTMP, N, 128, 256, 0); }
    // 18) final LN -> out_x
    ln_final<<<(N + 7)/8, 256>>>(gn, bn, out_x, N);
}

// round 5
// speedup vs baseline: 2.0770x; 1.7128x over previous
#include <cuda_runtime.h>
#include <math.h>

#define EMAX 320000
#define NMAX 10000
#define HS   (1<<20)
#define PPW  1024   // PP GEMM width: [We1_e 384 | We1_rev 384 | Wpe 128 | Wg1 64 | pad 64]
#define INIT_LIMIT ((long long)(NMAX)*128 > (long long)HS ? (long long)(NMAX)*128 : (long long)HS)

// ---------------- scratch (static device arrays; no allocation) ----------------
__device__ long long g_hkey[HS];
__device__ int       g_hval[HS];
__device__ float g_gates[EMAX];
__device__ int   g_rev[EMAX];
__device__ float g_PP[(long long)EMAX*PPW];
__device__ float g_XX[NMAX*768];
__device__ float g_h1[(long long)EMAX*384];
__device__ float g_etmp[(long long)EMAX*128];
__device__ float g_qx[NMAX*128];
__device__ float g_vx[NMAX*128];
__device__ float g_seg[NMAX*128];
__device__ float g_subj[NMAX*128];
__device__ float g_obj[NMAX*128];
__device__ float g_cnts[NMAX];
__device__ float g_cntd[NMAX];
__device__ float g_twin_in[NMAX*256];
__device__ float g_twin[NMAX*128];
__device__ float g_xcat[NMAX*256];
__device__ float g_ph[NMAX*256];
__device__ float g_ptmp[NMAX*128];
__device__ float g_BpE[128*PPW];
__device__ float g_BpN[128*768];
__device__ float g_biasPP[PPW];

// ---------------- helpers ----------------
__device__ __forceinline__ unsigned hash64(long long k){
    unsigned long long z = (unsigned long long)k;
    z *= 0x9E3779B97F4A7C15ull;
    z ^= z >> 29; z *= 0xBF58476D1CE4E5B9ull; z ^= z >> 32;
    return (unsigned)z;
}

__device__ __forceinline__ void atomicMaxF(float* addr, float v){
    if (v >= 0.f) atomicMax((int*)addr, __float_as_int(v));
    else          atomicMin((unsigned int*)addr, __float_as_uint(v));
}

__device__ __forceinline__ unsigned f2tf(float f){
    unsigned u;
    asm("cvt.rna.tf32.f32 %0, %1;" : "=r"(u) : "f"(f));
    return u;
}

#define MMA_TF32(c, a0,a1,a2,a3, b0,b1) \
    asm volatile("mma.sync.aligned.m16n8k8.row.col.f32.tf32.tf32.f32 " \
        "{%0,%1,%2,%3}, {%4,%5,%6,%7}, {%8,%9}, {%0,%1,%2,%3};" \
        : "+f"((c)[0]),"+f"((c)[1]),"+f"((c)[2]),"+f"((c)[3]) \
        : "r"(a0),"r"(a1),"r"(a2),"r"(a3),"r"(b0),"r"(b1))

// ---------------- init ----------------
__global__ void init_kernel(int N){
    long long stride = (long long)gridDim.x * blockDim.x;
    long long limit = INIT_LIMIT;
    for (long long i = (long long)blockIdx.x*blockDim.x + threadIdx.x; i < limit; i += stride){
        if (i < HS){
            g_hkey[i] = -1LL;
            g_hval[i] = 0x7fffffff;
        }
        if (i < (long long)N*128){
            g_seg[i]  = __int_as_float(0xff800000); // -inf
            g_subj[i] = 0.f;
            g_obj[i]  = 0.f;
        }
        if (i < N){ g_cnts[i] = 0.f; g_cntd[i] = 0.f; }
    }
}

// ---------------- repack: B for the big edge GEMM [128, PPW] ----------------
__global__ void repack_We1(const float* __restrict__ We1,
                           const float* __restrict__ Wpe,
                           const float* __restrict__ Wg1){
    int i = blockIdx.x*blockDim.x + threadIdx.x;
    if (i >= 128*PPW) return;
    int k = i / PPW, j = i % PPW;
    float v;
    if      (j < 384)  v = We1[(128+k)*384 + j];          // edge term
    else if (j < 768)  v = We1[(256+k)*384 + (j-384)];    // rev term
    else if (j < 896)  v = Wpe[k*128 + (j-768)];          // pe projection
    else if (j < 960)  v = Wg1[k*64 + (j-896)];           // gate hidden
    else               v = 0.f;                            // pad
    g_BpE[i] = v;
}

__global__ void repack_BpN_bias(const float* __restrict__ We1,
                                const float* __restrict__ bpe,
                                const float* __restrict__ bg1){
    int i = blockIdx.x*blockDim.x + threadIdx.x;
    if (i < 128*768){
        int k = i / 768, j = i % 768;
        g_BpN[i] = (j < 384) ? We1[k*384 + j] : We1[(384+k)*384 + (j-384)];
    }
    if (i < PPW){
        float v = 0.f;
        if      (i >= 768 && i < 896) v = bpe[i-768];
        else if (i >= 896 && i < 960) v = bg1[i-896];
        g_biasPP[i] = v;
    }
}

// ---------------- hash insert (+ degree counts) ----------------
__global__ void hash_insert(const int* __restrict__ src, const int* __restrict__ dst,
                            int E, int N){
    int e = blockIdx.x*blockDim.x + threadIdx.x;
    if (e >= E) return;
    int s = src[e], d = dst[e];
    long long key = (long long)s * N + d;
    unsigned slot = hash64(key) & (HS-1);
    for (;;){
        unsigned long long prev = atomicCAS((unsigned long long*)&g_hkey[slot],
                                            0xFFFFFFFFFFFFFFFFull,
                                            (unsigned long long)key);
        if (prev == 0xFFFFFFFFFFFFFFFFull || (long long)prev == key){
            atomicMin(&g_hval[slot], e);
            break;
        }
        slot = (slot + 1) & (HS-1);
    }
    atomicAdd(&g_cnts[s], 1.f);
    atomicAdd(&g_cntd[d], 1.f);
}

// ---------------- reverse-edge lookup ----------------
__global__ void rev_lookup(const int* __restrict__ src, const int* __restrict__ dst,
                           int E, int N){
    int e = blockIdx.x*blockDim.x + threadIdx.x;
    if (e >= E) return;
    long long rkey = (long long)dst[e] * N + src[e];
    unsigned slot = hash64(rkey) & (HS-1);
    int r = -1;
    for (;;){
        long long k = g_hkey[slot];
        if (k == -1LL) break;
        if (k == rkey){ r = g_hval[slot]; break; }
        slot = (slot + 1) & (HS-1);
    }
    g_rev[e] = r;
}

// ---------------- gate reduce ----------------
__global__ __launch_bounds__(256) void gate_reduce(
        const float* __restrict__ Wg2, const float* __restrict__ bg2, int E){
    long long e = (long long)blockIdx.x * 8 + (threadIdx.x >> 5);
    if (e >= E) return;
    int lane = threadIdx.x & 31;
    const float* row = g_PP + e*PPW + 896;
    float2 v = *(const float2*)&row[lane*2];
    float w0 = __ldg(&Wg2[lane*2]);
    float w1 = __ldg(&Wg2[lane*2+1]);
    float p = fmaxf(v.x, 0.f)*w0 + fmaxf(v.y, 0.f)*w1;
    #pragma unroll
    for (int off = 16; off; off >>= 1) p += __shfl_xor_sync(0xffffffffu, p, off);
    if (lane == 0)
        g_gates[e] = 1.f / (1.f + __expf(-(p + bg2[0])));
}

// ---------------- TF32 tensor-core GEMM: C = act(A[MxK] @ B[KxNw] + bias) ----------------
// Block: 256 thr = 8 warps (2m x 4n). Block tile 128x128, warp tile 64x32, K-step 32.
__global__ __launch_bounds__(256, 2) void tgemm128(
        const float* __restrict__ A, const float* __restrict__ B,
        const float* __restrict__ bias, float* __restrict__ C,
        int M, int Nw, int K, int relu){
    __shared__ unsigned As[128][36];   // padded: frag loads conflict-free
    __shared__ unsigned Bs[32][136];

    int tid  = threadIdx.x;
    int lane = tid & 31, wid = tid >> 5;
    int warp_m = wid >> 2, warp_n = wid & 3;
    int grp = lane >> 2, tig = lane & 3;
    int bm = blockIdx.y, bn = blockIdx.x;

    // global load mapping
    int arow = tid >> 3;            // 0..31
    int acol = (tid & 7) << 2;      // 0,4,..28
    int brow = tid >> 6;            // 0..3 (x2 stride 4 → rows 0..7)... use t>>5 pattern below
    // B: 32 rows x 128 cols: thread covers (t>>5) + r*8 rows, col (t&31)*4
    int brow0 = tid >> 5;           // 0..7
    int bcol  = (tid & 31) << 2;

    float acc[4][4][4];
    #pragma unroll
    for (int i=0;i<4;i++)
        #pragma unroll
        for (int j=0;j<4;j++)
            #pragma unroll
            for (int r=0;r<4;r++) acc[i][j][r] = 0.f;

    int T = K >> 5;
    float4 apf[4], bpf[4];

    // prologue: load tile 0
    {
        #pragma unroll
        for (int r = 0; r < 4; r++){
            int grow = bm*128 + arow + r*32;
            apf[r] = (grow < M) ? *(const float4*)(A + (size_t)grow*K + acol)
                                : make_float4(0,0,0,0);
        }
        #pragma unroll
        for (int r = 0; r < 4; r++){
            int gk = brow0 + r*8;
            bpf[r] = *(const float4*)(B + (size_t)gk*Nw + bn*128 + bcol);
        }
    }

    for (int t = 0; t < T; t++){
        // store prefetched tile to smem (convert to tf32)
        #pragma unroll
        for (int r = 0; r < 4; r++){
            unsigned* d = &As[arow + r*32][acol];
            d[0] = f2tf(apf[r].x); d[1] = f2tf(apf[r].y);
            d[2] = f2tf(apf[r].z); d[3] = f2tf(apf[r].w);
        }
        #pragma unroll
        for (int r = 0; r < 4; r++){
            unsigned* d = &Bs[brow0 + r*8][bcol];
            d[0] = f2tf(bpf[r].x); d[1] = f2tf(bpf[r].y);
            d[2] = f2tf(bpf[r].z); d[3] = f2tf(bpf[r].w);
        }
        __syncthreads();

        // prefetch next tile
        if (t+1 < T){
            int koff = (t+1) << 5;
            #pragma unroll
            for (int r = 0; r < 4; r++){
                int grow = bm*128 + arow + r*32;
                apf[r] = (grow < M) ? *(const float4*)(A + (size_t)grow*K + koff + acol)
                                    : make_float4(0,0,0,0);
            }
            #pragma unroll
            for (int r = 0; r < 4; r++){
                int gk = koff + brow0 + r*8;
                bpf[r] = *(const float4*)(B + (size_t)gk*Nw + bn*128 + bcol);
            }
        }

        // compute: 4 k-steps of m16n8k8
        #pragma unroll
        for (int ks = 0; ks < 4; ks++){
            int kc = (ks << 3) + tig;
            unsigned a[4][4], b[4][2];
            #pragma unroll
            for (int mt = 0; mt < 4; mt++){
                int rb = warp_m*64 + mt*16 + grp;
                a[mt][0] = As[rb][kc];
                a[mt][1] = As[rb+8][kc];
                a[mt][2] = As[rb][kc+4];
                a[mt][3] = As[rb+8][kc+4];
            }
            #pragma unroll
            for (int nt = 0; nt < 4; nt++){
                int cb = warp_n*32 + nt*8 + grp;
                b[nt][0] = Bs[(ks<<3) + tig][cb];
                b[nt][1] = Bs[(ks<<3) + tig + 4][cb];
            }
            #pragma unroll
            for (int mt = 0; mt < 4; mt++)
                #pragma unroll
                for (int nt = 0; nt < 4; nt++)
                    MMA_TF32(acc[mt][nt], a[mt][0],a[mt][1],a[mt][2],a[mt][3],
                             b[nt][0], b[nt][1]);
        }
        __syncthreads();
    }

    // epilogue
    #pragma unroll
    for (int mt = 0; mt < 4; mt++){
        int row0 = bm*128 + warp_m*64 + mt*16 + grp;
        #pragma unroll
        for (int nt = 0; nt < 4; nt++){
            int col = bn*128 + warp_n*32 + nt*8 + tig*2;
            float b0 = bias ? __ldg(&bias[col])   : 0.f;
            float b1 = bias ? __ldg(&bias[col+1]) : 0.f;
            float v0 = acc[mt][nt][0] + b0;
            float v1 = acc[mt][nt][1] + b1;
            float v2 = acc[mt][nt][2] + b0;
            float v3 = acc[mt][nt][3] + b1;
            if (relu){
                v0 = fmaxf(v0,0.f); v1 = fmaxf(v1,0.f);
                v2 = fmaxf(v2,0.f); v3 = fmaxf(v3,0.f);
            }
            if (row0 < M)     *(float2*)&C[(size_t)row0*Nw + col]     = make_float2(v0,v1);
            if (row0+8 < M)   *(float2*)&C[(size_t)(row0+8)*Nw + col] = make_float2(v2,v3);
        }
    }
}

// ---------------- fp32 double-buffered SGEMM (node-sized GEMMs) ----------------
__global__ __launch_bounds__(256) void sgemm128(
        const float* __restrict__ A, const float* __restrict__ B,
        const float* __restrict__ bias, float* __restrict__ C,
        int M, int Nw, int K, int relu){
    __shared__ float As[2][8][128];
    __shared__ float Bs[2][8][128];
    int tid = threadIdx.x;
    int bm = blockIdx.y, bn = blockIdx.x;

    int rowA = tid >> 1;
    int colA = (tid & 1) << 2;
    int rowB = tid >> 5;
    int colB = (tid & 31) << 2;
    int gRowA = bm*128 + rowA;
    int arow_ok = gRowA < M;

    const float* Ab = A + (size_t)gRowA * K + colA;
    const float* Bb = B + (size_t)rowB * Nw + bn*128 + colB;

    float acc[8][8];
    #pragma unroll
    for (int i=0;i<8;i++)
        #pragma unroll
        for (int j=0;j<8;j++) acc[i][j] = 0.f;

    int tr = (tid >> 4) << 3;
    int tc = (tid & 15) << 3;
    int T = K >> 3;

    {
        float4 av = arow_ok ? *(const float4*)Ab : make_float4(0,0,0,0);
        float4 bv = *(const float4*)Bb;
        As[0][colA+0][rowA] = av.x; As[0][colA+1][rowA] = av.y;
        As[0][colA+2][rowA] = av.z; As[0][colA+3][rowA] = av.w;
        *(float4*)&Bs[0][rowB][colB] = bv;
    }
    __syncthreads();

    int p = 0;
    for (int t = 0; t < T; t++){
        float4 av2 = make_float4(0,0,0,0), bv2 = make_float4(0,0,0,0);
        if (t+1 < T){
            if (arow_ok) av2 = *(const float4*)(Ab + (t+1)*8);
            bv2 = *(const float4*)(Bb + (size_t)(t+1)*8*Nw);
        }
        #pragma unroll
        for (int k = 0; k < 8; k++){
            float4 a0 = *(const float4*)&As[p][k][tr];
            float4 a1 = *(const float4*)&As[p][k][tr+4];
            float4 b0 = *(const float4*)&Bs[p][k][tc];
            float4 b1 = *(const float4*)&Bs[p][k][tc+4];
            float ar[8] = {a0.x,a0.y,a0.z,a0.w,a1.x,a1.y,a1.z,a1.w};
            float br[8] = {b0.x,b0.y,b0.z,b0.w,b1.x,b1.y,b1.z,b1.w};
            #pragma unroll
            for (int i=0;i<8;i++)
                #pragma unroll
                for (int j=0;j<8;j++) acc[i][j] += ar[i]*br[j];
        }
        if (t+1 < T){
            int q = p ^ 1;
            As[q][colA+0][rowA] = av2.x; As[q][colA+1][rowA] = av2.y;
            As[q][colA+2][rowA] = av2.z; As[q][colA+3][rowA] = av2.w;
            *(float4*)&Bs[q][rowB][colB] = bv2;
            __syncthreads();
            p = q;
        }
    }

    #pragma unroll
    for (int i = 0; i < 8; i++){
        int row = bm*128 + tr + i;
        if (row >= M) break;
        #pragma unroll
        for (int j = 0; j < 8; j += 4){
            int col = bn*128 + tc + j;
            float4 o;
            float b0 = bias ? bias[col+0] : 0.f;
            float b1 = bias ? bias[col+1] : 0.f;
            float b2 = bias ? bias[col+2] : 0.f;
            float b3 = bias ? bias[col+3] : 0.f;
            o.x = acc[i][j+0] + b0;
            o.y = acc[i][j+1] + b1;
            o.z = acc[i][j+2] + b2;
            o.w = acc[i][j+3] + b3;
            if (relu){
                o.x = fmaxf(o.x,0.f); o.y = fmaxf(o.y,0.f);
                o.z = fmaxf(o.z,0.f); o.w = fmaxf(o.w,0.f);
            }
            *(float4*)&C[(size_t)row*Nw + col] = o;
        }
    }
}

// ---------------- combine gathered pieces -> h1 = relu(...) ----------------
__global__ __launch_bounds__(128) void build_h1(
        const int* __restrict__ src, const int* __restrict__ dst,
        const float* __restrict__ be1, int E){
    long long e = blockIdx.x;
    int t = threadIdx.x;
    int s = src[e], d = dst[e], rv = g_rev[e];
    float g = g_gates[e];
    const float* xs = g_XX + (size_t)s*768;
    const float* xd = g_XX + (size_t)d*768 + 384;
    const float* pp = g_PP + e*PPW;
    const float* pr = (rv >= 0) ? (g_PP + (size_t)rv*PPW + 384) : 0;
    #pragma unroll
    for (int r = 0; r < 3; r++){
        int j = t + r*128;
        float v = be1[j] + xs[j] + pp[j] + xd[j];
        if (rv >= 0) v += g * pr[j];
        g_h1[e*384 + j] = fmaxf(v, 0.f);
    }
}

// ---------------- LayerNorm over edge rows + subj/obj segment sums ----------------
__global__ __launch_bounds__(256) void ln_edge(
        const float* __restrict__ ge, const float* __restrict__ be,
        const int* __restrict__ src, const int* __restrict__ dst,
        float* __restrict__ out_edge, int E){
    long long e = (long long)blockIdx.x * 8 + (threadIdx.x >> 5);
    if (e >= E) return;
    int lane = threadIdx.x & 31;
    const float* row = g_etmp + e*128;
    float4 v = *(const float4*)&row[lane*4];
    float s  = v.x + v.y + v.z + v.w;
    float ss = v.x*v.x + v.y*v.y + v.z*v.z + v.w*v.w;
    #pragma unroll
    for (int off = 16; off; off >>= 1){
        s  += __shfl_xor_sync(0xffffffffu, s,  off);
        ss += __shfl_xor_sync(0xffffffffu, ss, off);
    }
    float mean = s * (1.f/128.f);
    float var  = ss * (1.f/128.f) - mean*mean;
    float rstd = rsqrtf(var + 1e-5f);
    int sN = src[e], dN = dst[e];
    float vv[4] = {v.x, v.y, v.z, v.w};
    #pragma unroll
    for (int q = 0; q < 4; q++){
        int c = lane*4 + q;
        float val = (vv[q] - mean) * rstd * ge[c] + be[c];
        out_edge[e*128 + c] = val;
        atomicAdd(&g_subj[(size_t)sN*128 + c], val);
        atomicAdd(&g_obj [(size_t)dN*128 + c], val);
    }
}

// ---------------- attention: MLP (head-amortized) + softmax + scatter-max ----------------
__global__ __launch_bounds__(256) void attention_kernel(
        const int* __restrict__ src, const int* __restrict__ dst,
        const float* __restrict__ A1, const float* __restrict__ a1,
        const float* __restrict__ A2, const float* __restrict__ a2,
        int E){
    __shared__ float sA1t[64*64];   // [c][o]
    __shared__ float sA2t[64*32];   // [c][o]
    __shared__ float sa1[64], sa2[32];
    __shared__ float qe_s[4][256];
    __shared__ float v_s[4][128];
    __shared__ float h1_s[4][256];
    int t = threadIdx.x;
    for (int i = t; i < 4096; i += 256){ int o = i >> 6, c = i & 63; sA1t[c*64 + o] = A1[i]; }
    for (int i = t; i < 2048; i += 256){ int o = i >> 6, c = i & 63; sA2t[c*32 + o] = A2[i]; }
    if (t < 64) sa1[t] = a1[t];
    if (t < 32) sa2[t] = a2[t];
    __syncthreads();

    int slot = t >> 6;
    int o    = t & 63;

    for (long long e0 = (long long)blockIdx.x*4; e0 < E; e0 += (long long)gridDim.x*4){
        long long e = e0 + slot;
        bool ok = (e < E);
        int s = 0, d = 0;
        if (ok){ s = src[e]; d = dst[e]; }
        if (ok){
            if (o < 32){
                ((float4*)qe_s[slot])[o] = ((const float4*)(g_qx + (size_t)s*128))[o];
                ((float4*)v_s[slot])[o]  = ((const float4*)(g_vx + (size_t)d*128))[o];
            } else {
                ((float4*)qe_s[slot])[o] = ((const float4*)(g_PP + e*PPW + 768))[o-32];
            }
        }
        __syncthreads();

        float b1 = sa1[o];
        float c0 = b1, c1 = b1, c2 = b1, c3 = b1;
        #pragma unroll 8
        for (int c = 0; c < 64; c++){
            float w = sA1t[c*64 + o];
            float4 in = *(const float4*)&qe_s[slot][c*4];
            c0 += w*in.x; c1 += w*in.y; c2 += w*in.z; c3 += w*in.w;
        }
        float4 h1v = make_float4(fmaxf(c0,0.f), fmaxf(c1,0.f), fmaxf(c2,0.f), fmaxf(c3,0.f));
        *(float4*)&h1_s[slot][o*4] = h1v;
        __syncthreads();

        if (o < 32){
            float b2 = sa2[o];
            float p0 = b2, p1 = b2, p2 = b2, p3 = b2;
            #pragma unroll 8
            for (int c = 0; c < 64; c++){
                float w = sA2t[c*32 + o];
                float4 in = *(const float4*)&h1_s[slot][c*4];
                p0 += w*in.x; p1 += w*in.y; p2 += w*in.z; p3 += w*in.w;
            }
            if (ok){
                float vals[4] = {p0, p1, p2, p3};
                float4 vv = *(const float4*)&v_s[slot][o*4];
                float vvv[4] = {vv.x, vv.y, vv.z, vv.w};
                #pragma unroll
                for (int h = 0; h < 4; h++){
                    float m = vals[h];
                    #pragma unroll
                    for (int off = 16; off; off >>= 1)
                        m = fmaxf(m, __shfl_xor_sync(0xffffffffu, m, off));
                    float ex = __expf(vals[h] - m);
                    float sm = ex;
                    #pragma unroll
                    for (int off = 16; off; off >>= 1)
                        sm += __shfl_xor_sync(0xffffffffu, sm, off);
                    float prob = ex / sm;
                    atomicMaxF(&g_seg[(size_t)s*128 + o*4 + h], prob * vvv[h]);
                }
            }
        }
        __syncthreads();
    }
}

// ---------------- node-side glue ----------------
__global__ void build_twin_in(int N){
    int i = blockIdx.x*blockDim.x + threadIdx.x;
    if (i >= N*128) return;
    int n = i >> 7, c = i & 127;
    g_twin_in[(size_t)n*256 + c]       = g_subj[i] / fmaxf(g_cnts[n], 1.f);
    g_twin_in[(size_t)n*256 + 128 + c] = g_obj[i]  / fmaxf(g_cntd[n], 1.f);
}

__global__ void build_xcat(const float* __restrict__ x, int N){
    int i = blockIdx.x*blockDim.x + threadIdx.x;
    if (i >= N*128) return;
    int n = i >> 7, c = i & 127;
    g_xcat[(size_t)n*256 + c] = x[i];
    float s = (g_cnts[n] > 0.f) ? g_seg[i] : 0.f;
    s = fmaxf(s, 0.f);
    float tw = g_twin[i];
    g_xcat[(size_t)n*256 + 128 + c] = s * (1.f / (1.f + __expf(-tw)));
}

// ---------------- final LayerNorm ----------------
__global__ __launch_bounds__(256) void ln_final(
        const float* __restrict__ gn, const float* __restrict__ bn,
        float* __restrict__ out_x, int N){
    int n = blockIdx.x * 8 + (threadIdx.x >> 5);
    if (n >= N) return;
    int lane = threadIdx.x & 31;
    const float* row = g_ptmp + (size_t)n*128;
    float4 v = *(const float4*)&row[lane*4];
    float s  = v.x + v.y + v.z + v.w;
    float ss = v.x*v.x + v.y*v.y + v.z*v.z + v.w*v.w;
    #pragma unroll
    for (int off = 16; off; off >>= 1){
        s  += __shfl_xor_sync(0xffffffffu, s,  off);
        ss += __shfl_xor_sync(0xffffffffu, ss, off);
    }
    float mean = s * (1.f/128.f);
    float var  = ss * (1.f/128.f) - mean*mean;
    float rstd = rsqrtf(var + 1e-5f);
    float vv[4] = {v.x, v.y, v.z, v.w};
    #pragma unroll
    for (int q = 0; q < 4; q++){
        int c = lane*4 + q;
        out_x[(size_t)n*128 + c] = (vv[q] - mean) * rstd * gn[c] + bn[c];
    }
}

// ---------------- host ----------------
extern "C" void kernel_launch(void* const* d_in, const int* in_sizes, int n_in,
                              void* d_out, int out_size){
    const float* x    = (const float*)d_in[0];
    const float* ef   = (const float*)d_in[1];
    const int*   eidx = (const int*)  d_in[2];
    const float* Wg1  = (const float*)d_in[3];
    const float* bg1  = (const float*)d_in[4];
    const float* Wg2  = (const float*)d_in[5];
    const float* bg2  = (const float*)d_in[6];
    const float* We1  = (const float*)d_in[7];
    const float* be1  = (const float*)d_in[8];
    const float* We2  = (const float*)d_in[9];
    const float* be2  = (const float*)d_in[10];
    const float* ge   = (const float*)d_in[11];
    const float* beta_e=(const float*)d_in[12];
    const float* Wq   = (const float*)d_in[13];
    const float* bq   = (const float*)d_in[14];
    const float* Wpe  = (const float*)d_in[15];
    const float* bpe  = (const float*)d_in[16];
    const float* Wv   = (const float*)d_in[17];
    const float* bv   = (const float*)d_in[18];
    const float* A1   = (const float*)d_in[19];
    const float* a1   = (const float*)d_in[20];
    const float* A2   = (const float*)d_in[21];
    const float* a2   = (const float*)d_in[22];
    const float* Wt   = (const float*)d_in[23];
    const float* bt   = (const float*)d_in[24];
    const float* Wp1  = (const float*)d_in[25];
    const float* bp1  = (const float*)d_in[26];
    const float* Wp2  = (const float*)d_in[27];
    const float* bp2  = (const float*)d_in[28];
    const float* gn   = (const float*)d_in[29];
    const float* bn   = (const float*)d_in[30];

    int N = in_sizes[0] / 128;
    int E = in_sizes[2] / 2;
    const int* src = eidx;
    const int* dst = eidx + E;

    float* out_x = (float*)d_out;                        // [N,128]
    float* out_e = (float*)d_out + (size_t)N * 128;      // [E,128]

    float *pPP, *pXX, *pH1, *pETMP, *pQX, *pVX;
    float *pTIN, *pTWIN, *pXCAT, *pPH, *pPTMP, *pBpE, *pBpN, *pBias;
    cudaGetSymbolAddress((void**)&pPP,   g_PP);
    cudaGetSymbolAddress((void**)&pXX,   g_XX);
    cudaGetSymbolAddress((void**)&pH1,   g_h1);
    cudaGetSymbolAddress((void**)&pETMP, g_etmp);
    cudaGetSymbolAddress((void**)&pQX,   g_qx);
    cudaGetSymbolAddress((void**)&pVX,   g_vx);
    cudaGetSymbolAddress((void**)&pTIN,  g_twin_in);
    cudaGetSymbolAddress((void**)&pTWIN, g_twin);
    cudaGetSymbolAddress((void**)&pXCAT, g_xcat);
    cudaGetSymbolAddress((void**)&pPH,   g_ph);
    cudaGetSymbolAddress((void**)&pPTMP, g_ptmp);
    cudaGetSymbolAddress((void**)&pBpE,  g_BpE);
    cudaGetSymbolAddress((void**)&pBpN,  g_BpN);
    cudaGetSymbolAddress((void**)&pBias, g_biasPP);

    // 1) init state
    init_kernel<<<2048, 256>>>(N);
    // 2) repack weights
    repack_We1<<<(128*PPW + 255)/256, 256>>>(We1, Wpe, Wg1);
    repack_BpN_bias<<<(128*768 + 255)/256, 256>>>(We1, bpe, bg1);
    // 3) hash insert + degree counts
    hash_insert<<<(E + 255)/256, 256>>>(src, dst, E, N);
    // 4) reverse lookup
    rev_lookup<<<(E + 255)/256, 256>>>(src, dst, E, N);
    // 5) node part of nn_edge layer1: XX = x @ BpN   [N,768] (fp32)
    { dim3 g(768/128, (N+127)/128); sgemm128<<<g,256>>>(x, pBpN, 0, pXX, N, 768, 128, 0); }
    // 6) big edge GEMM (TF32 tensor cores): PP = ef @ BpE (+bias)  [E,1024]
    { dim3 g(PPW/128, (E+127)/128); tgemm128<<<g,256>>>(ef, pBpE, pBias, pPP, E, PPW, 128, 0); }
    // 7) gate sigmoid reduce
    gate_reduce<<<(E + 7)/8, 256>>>(Wg2, bg2, E);
    // 8) combine -> h1 = relu(...)
    build_h1<<<E, 128>>>(src, dst, be1, E);
    // 9) etmp = h1 @ We2 + be2 (TF32 tensor cores)
    { dim3 g(1, (E+127)/128); tgemm128<<<g,256>>>(pH1, We2, be2, pETMP, E, 128, 384, 0); }
    // 10) LN over edge rows -> out_e, and subj/obj segment sums
    ln_edge<<<(E + 7)/8, 256>>>(ge, beta_e, src, dst, out_e, E);
    // 11) q/v projections (node-sized, fp32)
    { dim3 g(1, (N+127)/128); sgemm128<<<g,256>>>(x, Wq, bq, pQX, N, 128, 128, 0); }
    { dim3 g(1, (N+127)/128); sgemm128<<<g,256>>>(x, Wv, bv, pVX, N, 128, 128, 0); }
    // 12) attention + scatter-max
    attention_kernel<<<8192, 256>>>(src, dst, A1, a1, A2, a2, E);
    // 13) twin input (segment means)
    build_twin_in<<<(N*128 + 255)/256, 256>>>(N);
    // 14) twin = twin_in @ Wt + bt
    { dim3 g(1, (N+127)/128); sgemm128<<<g,256>>>(pTIN, Wt, bt, pTWIN, N, 128, 256, 0); }
    // 15) xcat = [x, relu(gated seg-max) * sigmoid(twin)]
    build_xcat<<<(N*128 + 255)/256, 256>>>(x, N);
    // 16) ph = relu(xcat @ Wp1 + bp1)
    { dim3 g(256/128, (N+127)/128); sgemm128<<<g,256>>>(pXCAT, Wp1, bp1, pPH, N, 256, 256, 1); }
    // 17) ptmp = ph @ Wp2 + bp2
    { dim3 g(1, (N+127)/128); sgemm128<<<g,256>>>(pPH, Wp2, bp2, pPTMP, N, 128, 256, 0); }
    // 18) final LN -> out_x
    ln_final<<<(N + 7)/8, 256>>>(gn, bn, out_x, N);
}

// round 7
// speedup vs baseline: 2.4853x; 1.1966x over previous
#include <cuda_runtime.h>
#include <math.h>

#define EMAX 320000
#define NMAX 10000
#define HS   (1<<20)
#define PPW  1024   // PP stride: [We1_e 384 | We1_rev 384 | Wpe 128 | gate-hidden 64 | pad 64]
#define INIT_LIMIT ((long long)(NMAX)*128 > (long long)HS ? (long long)(NMAX)*128 : (long long)HS)

// ---------------- scratch ----------------
__device__ long long g_hkey[HS];
__device__ int       g_hval[HS];
__device__ float g_gates[EMAX];
__device__ int   g_rev[EMAX];
__device__ float g_PP[(long long)EMAX*PPW];
__device__ float g_XX[NMAX*768];
__device__ float g_qv[NMAX*256];
__device__ float g_seg[NMAX*128];
__device__ float g_subj[NMAX*128];
__device__ float g_obj[NMAX*128];
__device__ float g_cnts[NMAX];
__device__ float g_cntd[NMAX];
__device__ float g_twin_in[NMAX*256];
__device__ float g_xcat[NMAX*256];
__device__ float g_ph[NMAX*256];
__device__ float g_ptmp[NMAX*128];
__device__ float g_BpE[128*PPW];
__device__ float g_BpN[128*768];
__device__ float g_Wqv[128*256];
__device__ float g_bqv[256];
__device__ float g_biasPP[PPW];

// ---------------- helpers ----------------
__device__ __forceinline__ unsigned hash64(long long k){
    unsigned long long z = (unsigned long long)k;
    z *= 0x9E3779B97F4A7C15ull;
    z ^= z >> 29; z *= 0xBF58476D1CE4E5B9ull; z ^= z >> 32;
    return (unsigned)z;
}

__device__ __forceinline__ void atomicMaxF(float* addr, float v){
    if (v >= 0.f) atomicMax((int*)addr, __float_as_int(v));
    else          atomicMin((unsigned int*)addr, __float_as_uint(v));
}

__device__ __forceinline__ void red2(float* p, float a, float b){
    asm volatile("red.global.add.v2.f32 [%0], {%1, %2};" :: "l"(p), "f"(a), "f"(b) : "memory");
}

__device__ __forceinline__ unsigned f2tf(float f){
    unsigned u;
    asm("cvt.rna.tf32.f32 %0, %1;" : "=r"(u) : "f"(f));
    return u;
}

#define MMA_TF32(c, a0,a1,a2,a3, b0,b1) \
    asm volatile("mma.sync.aligned.m16n8k8.row.col.f32.tf32.tf32.f32 " \
        "{%0,%1,%2,%3}, {%4,%5,%6,%7}, {%8,%9}, {%0,%1,%2,%3};" \
        : "+f"((c)[0]),"+f"((c)[1]),"+f"((c)[2]),"+f"((c)[3]) \
        : "r"(a0),"r"(a1),"r"(a2),"r"(a3),"r"(b0),"r"(b1))

// ---------------- init ----------------
__global__ void init_kernel(int N){
    long long stride = (long long)gridDim.x * blockDim.x;
    long long limit = INIT_LIMIT;
    for (long long i = (long long)blockIdx.x*blockDim.x + threadIdx.x; i < limit; i += stride){
        if (i < HS){
            g_hkey[i] = -1LL;
            g_hval[i] = 0x7fffffff;
        }
        if (i < (long long)N*128){
            g_seg[i]  = __int_as_float(0xff800000); // -inf
            g_subj[i] = 0.f;
            g_obj[i]  = 0.f;
        }
        if (i < N){ g_cnts[i] = 0.f; g_cntd[i] = 0.f; }
    }
}

// ---------------- repacks ----------------
__global__ void repack_We1(const float* __restrict__ We1,
                           const float* __restrict__ Wpe,
                           const float* __restrict__ Wg1){
    int i = blockIdx.x*blockDim.x + threadIdx.x;
    if (i >= 128*PPW) return;
    int k = i / PPW, j = i % PPW;
    float v;
    if      (j < 384)  v = We1[(128+k)*384 + j];
    else if (j < 768)  v = We1[(256+k)*384 + (j-384)];
    else if (j < 896)  v = Wpe[k*128 + (j-768)];
    else if (j < 960)  v = Wg1[k*64 + (j-896)];
    else               v = 0.f;
    g_BpE[i] = v;
}

__global__ void repack_BpN_bias(const float* __restrict__ We1,
                                const float* __restrict__ bpe,
                                const float* __restrict__ bg1){
    int i = blockIdx.x*blockDim.x + threadIdx.x;
    if (i < 128*768){
        int k = i / 768, j = i % 768;
        g_BpN[i] = (j < 384) ? We1[k*384 + j] : We1[(384+k)*384 + (j-384)];
    }
    if (i < PPW){
        float v = 0.f;
        if      (i >= 768 && i < 896) v = bpe[i-768];
        else if (i >= 896 && i < 960) v = bg1[i-896];
        g_biasPP[i] = v;
    }
}

__global__ void repack_qv(const float* __restrict__ Wq, const float* __restrict__ bq,
                          const float* __restrict__ Wv, const float* __restrict__ bv){
    int i = blockIdx.x*blockDim.x + threadIdx.x;
    if (i < 128*256){
        int k = i / 256, j = i % 256;
        g_Wqv[i] = (j < 128) ? Wq[k*128 + j] : Wv[k*128 + (j-128)];
    }
    if (i < 256) g_bqv[i] = (i < 128) ? bq[i] : bv[i-128];
}

// ---------------- hash insert (+ degree counts) ----------------
__global__ void hash_insert(const int* __restrict__ src, const int* __restrict__ dst,
                            int E, int N){
    int e = blockIdx.x*blockDim.x + threadIdx.x;
    if (e >= E) return;
    int s = src[e], d = dst[e];
    long long key = (long long)s * N + d;
    unsigned slot = hash64(key) & (HS-1);
    for (;;){
        unsigned long long prev = atomicCAS((unsigned long long*)&g_hkey[slot],
                                            0xFFFFFFFFFFFFFFFFull,
                                            (unsigned long long)key);
        if (prev == 0xFFFFFFFFFFFFFFFFull || (long long)prev == key){
            atomicMin(&g_hval[slot], e);
            break;
        }
        slot = (slot + 1) & (HS-1);
    }
    atomicAdd(&g_cnts[s], 1.f);
    atomicAdd(&g_cntd[d], 1.f);
}

// ---------------- reverse-edge lookup ----------------
__global__ void rev_lookup(const int* __restrict__ src, const int* __restrict__ dst,
                           int E, int N){
    int e = blockIdx.x*blockDim.x + threadIdx.x;
    if (e >= E) return;
    long long rkey = (long long)dst[e] * N + src[e];
    unsigned slot = hash64(rkey) & (HS-1);
    int r = -1;
    for (;;){
        long long k = g_hkey[slot];
        if (k == -1LL) break;
        if (k == rkey){ r = g_hval[slot]; break; }
        slot = (slot + 1) & (HS-1);
    }
    g_rev[e] = r;
}

// ---------------- TF32 GEMM for PP with fused gate epilogue ----------------
// C = A[MxK] @ B[KxNw] + bias. When bn == gate_bn: skip store, compute
// gates = sigmoid(relu(acc+bias)[:,0:64] . Wg2 + bg2) instead.
__global__ __launch_bounds__(256, 2) void tgemm_pp(
        const float* __restrict__ A, const float* __restrict__ B,
        const float* __restrict__ bias, float* __restrict__ C,
        int M, int Nw, int K, int gate_bn,
        const float* __restrict__ Wg2, const float* __restrict__ bg2){
    __shared__ unsigned As[128][36];
    __shared__ unsigned Bs[32][136];
    __shared__ float gpart[128];

    int tid  = threadIdx.x;
    int lane = tid & 31, wid = tid >> 5;
    int warp_m = wid >> 2, warp_n = wid & 3;
    int grp = lane >> 2, tig = lane & 3;
    int bm = blockIdx.y, bn = blockIdx.x;

    if (tid < 128) gpart[tid] = 0.f;

    int arow = tid >> 3;
    int acol = (tid & 7) << 2;
    int brow0 = tid >> 5;
    int bcol  = (tid & 31) << 2;

    float acc[4][4][4];
    #pragma unroll
    for (int i=0;i<4;i++)
        #pragma unroll
        for (int j=0;j<4;j++)
            #pragma unroll
            for (int r=0;r<4;r++) acc[i][j][r] = 0.f;

    int T = K >> 5;
    float4 apf[4], bpf[4];

    {
        #pragma unroll
        for (int r = 0; r < 4; r++){
            int grow = bm*128 + arow + r*32;
            apf[r] = (grow < M) ? *(const float4*)(A + (size_t)grow*K + acol)
                                : make_float4(0,0,0,0);
        }
        #pragma unroll
        for (int r = 0; r < 4; r++){
            int gk = brow0 + r*8;
            bpf[r] = *(const float4*)(B + (size_t)gk*Nw + bn*128 + bcol);
        }
    }

    for (int t = 0; t < T; t++){
        #pragma unroll
        for (int r = 0; r < 4; r++){
            unsigned* d = &As[arow + r*32][acol];
            d[0] = f2tf(apf[r].x); d[1] = f2tf(apf[r].y);
            d[2] = f2tf(apf[r].z); d[3] = f2tf(apf[r].w);
        }
        #pragma unroll
        for (int r = 0; r < 4; r++){
            unsigned* d = &Bs[brow0 + r*8][bcol];
            d[0] = f2tf(bpf[r].x); d[1] = f2tf(bpf[r].y);
            d[2] = f2tf(bpf[r].z); d[3] = f2tf(bpf[r].w);
        }
        __syncthreads();

        if (t+1 < T){
            int koff = (t+1) << 5;
            #pragma unroll
            for (int r = 0; r < 4; r++){
                int grow = bm*128 + arow + r*32;
                apf[r] = (grow < M) ? *(const float4*)(A + (size_t)grow*K + koff + acol)
                                    : make_float4(0,0,0,0);
            }
            #pragma unroll
            for (int r = 0; r < 4; r++){
                int gk = koff + brow0 + r*8;
                bpf[r] = *(const float4*)(B + (size_t)gk*Nw + bn*128 + bcol);
            }
        }

        #pragma unroll
        for (int ks = 0; ks < 4; ks++){
            int kc = (ks << 3) + tig;
            unsigned a[4][4], b[4][2];
            #pragma unroll
            for (int mt = 0; mt < 4; mt++){
                int rb = warp_m*64 + mt*16 + grp;
                a[mt][0] = As[rb][kc];
                a[mt][1] = As[rb+8][kc];
                a[mt][2] = As[rb][kc+4];
                a[mt][3] = As[rb+8][kc+4];
            }
            #pragma unroll
            for (int nt = 0; nt < 4; nt++){
                int cb = warp_n*32 + nt*8 + grp;
                b[nt][0] = Bs[(ks<<3) + tig][cb];
                b[nt][1] = Bs[(ks<<3) + tig + 4][cb];
            }
            #pragma unroll
            for (int mt = 0; mt < 4; mt++)
                #pragma unroll
                for (int nt = 0; nt < 4; nt++)
                    MMA_TF32(acc[mt][nt], a[mt][0],a[mt][1],a[mt][2],a[mt][3],
                             b[nt][0], b[nt][1]);
        }
        __syncthreads();
    }

    if (bn == gate_bn){
        // gate path: local cols 0..63 hold gate hidden (global 896..959)
        #pragma unroll
        for (int mt = 0; mt < 4; mt++){
            float pa = 0.f, pb = 0.f;
            #pragma unroll
            for (int nt = 0; nt < 4; nt++){
                int lc = warp_n*32 + nt*8 + tig*2;
                if (lc < 64){
                    float w0 = __ldg(&Wg2[lc]);
                    float w1 = __ldg(&Wg2[lc+1]);
                    float b0 = __ldg(&bias[bn*128 + lc]);
                    float b1 = __ldg(&bias[bn*128 + lc + 1]);
                    pa += fmaxf(acc[mt][nt][0]+b0, 0.f)*w0 + fmaxf(acc[mt][nt][1]+b1, 0.f)*w1;
                    pb += fmaxf(acc[mt][nt][2]+b0, 0.f)*w0 + fmaxf(acc[mt][nt][3]+b1, 0.f)*w1;
                }
            }
            pa += __shfl_xor_sync(0xffffffffu, pa, 1);
            pa += __shfl_xor_sync(0xffffffffu, pa, 2);
            pb += __shfl_xor_sync(0xffffffffu, pb, 1);
            pb += __shfl_xor_sync(0xffffffffu, pb, 2);
            if (tig == 0){
                int ra = warp_m*64 + mt*16 + grp;
                atomicAdd(&gpart[ra], pa);
                atomicAdd(&gpart[ra+8], pb);
            }
        }
        __syncthreads();
        if (tid < 128){
            int e = bm*128 + tid;
            if (e < M)
                g_gates[e] = 1.f / (1.f + __expf(-(gpart[tid] + bg2[0])));
        }
    } else {
        #pragma unroll
        for (int mt = 0; mt < 4; mt++){
            int row0 = bm*128 + warp_m*64 + mt*16 + grp;
            #pragma unroll
            for (int nt = 0; nt < 4; nt++){
                int col = bn*128 + warp_n*32 + nt*8 + tig*2;
                float b0 = __ldg(&bias[col]);
                float b1 = __ldg(&bias[col+1]);
                if (row0 < M)
                    *(float2*)&C[(size_t)row0*Nw + col] =
                        make_float2(acc[mt][nt][0]+b0, acc[mt][nt][1]+b1);
                if (row0+8 < M)
                    *(float2*)&C[(size_t)(row0+8)*Nw + col] =
                        make_float2(acc[mt][nt][2]+b0, acc[mt][nt][3]+b1);
            }
        }
    }
}

// ---------------- fused: build_h1 + (h1@We2+be2) + LayerNorm + subj/obj scatter ----------------
// One block = 128 edges x full 128-col output row. K=384.
__global__ __launch_bounds__(256, 2) void edge_mlp2_ln(
        const int* __restrict__ src, const int* __restrict__ dst,
        const float* __restrict__ We2, const float* __restrict__ be1,
        const float* __restrict__ be2,
        const float* __restrict__ ge, const float* __restrict__ beta_e,
        float* __restrict__ out_edge, int E){
    __shared__ unsigned As[128][36];
    __shared__ unsigned Bs[32][136];
    __shared__ int   s_s[128], s_d[128], s_r[128];
    __shared__ float s_g[128];
    __shared__ float s_be2[128], s_ge[128], s_be[128];
    __shared__ float s_sum[128], s_sq[128];
    __shared__ float s_mean[128], s_rstd[128];

    int tid  = threadIdx.x;
    int lane = tid & 31, wid = tid >> 5;
    int warp_m = wid >> 2, warp_n = wid & 3;
    int grp = lane >> 2, tig = lane & 3;
    long long e0 = (long long)blockIdx.x * 128;

    if (tid < 128){
        long long e = e0 + tid;
        int s = 0, d = 0, r = -1; float g = 0.f;
        if (e < E){ s = src[e]; d = dst[e]; r = g_rev[e]; g = g_gates[e]; }
        s_s[tid] = s; s_d[tid] = d; s_r[tid] = r; s_g[tid] = g;
        s_be2[tid] = be2[tid]; s_ge[tid] = ge[tid]; s_be[tid] = beta_e[tid];
        s_sum[tid] = 0.f; s_sq[tid] = 0.f;
    }
    __syncthreads();

    int arow = tid >> 3;
    int acol = (tid & 7) << 2;
    int brow0 = tid >> 5;
    int bcol  = (tid & 31) << 2;

    float acc[4][4][4];
    #pragma unroll
    for (int i=0;i<4;i++)
        #pragma unroll
        for (int j=0;j<4;j++)
            #pragma unroll
            for (int r=0;r<4;r++) acc[i][j][r] = 0.f;

    const int T = 12;   // 384/32
    float4 apf[4], bpf[4];

    // h1 on-the-fly: h1[e][j] = relu(be1[j] + XX[s][j] + PP[e][j] + XX[d][384+j] + g*PP[rv][384+j])
    #define LOAD_A_TILE(koff) { \
        _Pragma("unroll") \
        for (int r = 0; r < 4; r++){ \
            int row = arow + r*32; \
            int j = (koff) + acol; \
            long long e = e0 + row; if (e >= E) e = E-1; \
            float4 pp = *(const float4*)(g_PP + (size_t)e*PPW + j); \
            float4 xs = *(const float4*)(g_XX + (size_t)s_s[row]*768 + j); \
            float4 xd = *(const float4*)(g_XX + (size_t)s_d[row]*768 + 384 + j); \
            float4 b1 = *(const float4*)(be1 + j); \
            int rv = s_r[row]; float g = s_g[row]; \
            float4 pr = make_float4(0,0,0,0); \
            if (rv >= 0) pr = *(const float4*)(g_PP + (size_t)rv*PPW + 384 + j); \
            apf[r].x = fmaxf(b1.x + xs.x + pp.x + xd.x + g*pr.x, 0.f); \
            apf[r].y = fmaxf(b1.y + xs.y + pp.y + xd.y + g*pr.y, 0.f); \
            apf[r].z = fmaxf(b1.z + xs.z + pp.z + xd.z + g*pr.z, 0.f); \
            apf[r].w = fmaxf(b1.w + xs.w + pp.w + xd.w + g*pr.w, 0.f); \
        } \
    }
    #define LOAD_B_TILE(koff) { \
        _Pragma("unroll") \
        for (int r = 0; r < 4; r++){ \
            int gk = (koff) + brow0 + r*8; \
            bpf[r] = *(const float4*)(We2 + (size_t)gk*128 + bcol); \
        } \
    }

    LOAD_A_TILE(0);
    LOAD_B_TILE(0);

    for (int t = 0; t < T; t++){
        #pragma unroll
        for (int r = 0; r < 4; r++){
            unsigned* dp = &As[arow + r*32][acol];
            dp[0] = f2tf(apf[r].x); dp[1] = f2tf(apf[r].y);
            dp[2] = f2tf(apf[r].z); dp[3] = f2tf(apf[r].w);
        }
        #pragma unroll
        for (int r = 0; r < 4; r++){
            unsigned* dp = &Bs[brow0 + r*8][bcol];
            dp[0] = f2tf(bpf[r].x); dp[1] = f2tf(bpf[r].y);
            dp[2] = f2tf(bpf[r].z); dp[3] = f2tf(bpf[r].w);
        }
        __syncthreads();

        if (t+1 < T){
            int koff = (t+1) << 5;
            LOAD_A_TILE(koff);
            LOAD_B_TILE(koff);
        }

        #pragma unroll
        for (int ks = 0; ks < 4; ks++){
            int kc = (ks << 3) + tig;
            unsigned a[4][4], b[4][2];
            #pragma unroll
            for (int mt = 0; mt < 4; mt++){
                int rb = warp_m*64 + mt*16 + grp;
                a[mt][0] = As[rb][kc];
                a[mt][1] = As[rb+8][kc];
                a[mt][2] = As[rb][kc+4];
                a[mt][3] = As[rb+8][kc+4];
            }
            #pragma unroll
            for (int nt = 0; nt < 4; nt++){
                int cb = warp_n*32 + nt*8 + grp;
                b[nt][0] = Bs[(ks<<3) + tig][cb];
                b[nt][1] = Bs[(ks<<3) + tig + 4][cb];
            }
            #pragma unroll
            for (int mt = 0; mt < 4; mt++)
                #pragma unroll
                for (int nt = 0; nt < 4; nt++)
                    MMA_TF32(acc[mt][nt], a[mt][0],a[mt][1],a[mt][2],a[mt][3],
                             b[nt][0], b[nt][1]);
        }
        __syncthreads();
    }

    // epilogue: add be2, row stats
    #pragma unroll
    for (int mt = 0; mt < 4; mt++){
        float pas = 0.f, paq = 0.f, pbs = 0.f, pbq = 0.f;
        #pragma unroll
        for (int nt = 0; nt < 4; nt++){
            int col = warp_n*32 + nt*8 + tig*2;
            float b0 = s_be2[col], b1 = s_be2[col+1];
            acc[mt][nt][0] += b0; acc[mt][nt][1] += b1;
            acc[mt][nt][2] += b0; acc[mt][nt][3] += b1;
            pas += acc[mt][nt][0] + acc[mt][nt][1];
            paq += acc[mt][nt][0]*acc[mt][nt][0] + acc[mt][nt][1]*acc[mt][nt][1];
            pbs += acc[mt][nt][2] + acc[mt][nt][3];
            pbq += acc[mt][nt][2]*acc[mt][nt][2] + acc[mt][nt][3]*acc[mt][nt][3];
        }
        pas += __shfl_xor_sync(0xffffffffu, pas, 1);
        pas += __shfl_xor_sync(0xffffffffu, pas, 2);
        paq += __shfl_xor_sync(0xffffffffu, paq, 1);
        paq += __shfl_xor_sync(0xffffffffu, paq, 2);
        pbs += __shfl_xor_sync(0xffffffffu, pbs, 1);
        pbs += __shfl_xor_sync(0xffffffffu, pbs, 2);
        pbq += __shfl_xor_sync(0xffffffffu, pbq, 1);
        pbq += __shfl_xor_sync(0xffffffffu, pbq, 2);
        if (tig == 0){
            int ra = warp_m*64 + mt*16 + grp;
            atomicAdd(&s_sum[ra],   pas);
            atomicAdd(&s_sq[ra],    paq);
            atomicAdd(&s_sum[ra+8], pbs);
            atomicAdd(&s_sq[ra+8],  pbq);
        }
    }
    __syncthreads();
    if (tid < 128){
        float m = s_sum[tid] * (1.f/128.f);
        float v = s_sq[tid] * (1.f/128.f) - m*m;
        s_mean[tid] = m;
        s_rstd[tid] = rsqrtf(v + 1e-5f);
    }
    __syncthreads();

    // normalize, store, scatter
    #pragma unroll
    for (int mt = 0; mt < 4; mt++){
        int ra = warp_m*64 + mt*16 + grp;
        int rb = ra + 8;
        long long ea = e0 + ra, eb = e0 + rb;
        float ma = s_mean[ra], rsa = s_rstd[ra];
        float mb = s_mean[rb], rsb = s_rstd[rb];
        int sa = s_s[ra], da = s_d[ra];
        int sb = s_s[rb], db = s_d[rb];
        #pragma unroll
        for (int nt = 0; nt < 4; nt++){
            int col = warp_n*32 + nt*8 + tig*2;
            float gsc0 = s_ge[col], gsc1 = s_ge[col+1];
            float bsc0 = s_be[col], bsc1 = s_be[col+1];
            if (ea < E){
                float o0 = (acc[mt][nt][0]-ma)*rsa*gsc0 + bsc0;
                float o1 = (acc[mt][nt][1]-ma)*rsa*gsc1 + bsc1;
                *(float2*)&out_edge[ea*128 + col] = make_float2(o0, o1);
                red2(&g_subj[(size_t)sa*128 + col], o0, o1);
                red2(&g_obj [(size_t)da*128 + col], o0, o1);
            }
            if (eb < E){
                float o2 = (acc[mt][nt][2]-mb)*rsb*gsc0 + bsc0;
                float o3 = (acc[mt][nt][3]-mb)*rsb*gsc1 + bsc1;
                *(float2*)&out_edge[eb*128 + col] = make_float2(o2, o3);
                red2(&g_subj[(size_t)sb*128 + col], o2, o3);
                red2(&g_obj [(size_t)db*128 + col], o2, o3);
            }
        }
    }
}

// ---------------- fp32 SGEMM (node-sized) with epilogue modes ----------------
// mode 0: none, 1: relu, 2: twin epilogue (write xcat[:,128+col], ldc applies)
__global__ __launch_bounds__(256) void sgemm128(
        const float* __restrict__ A, const float* __restrict__ B,
        const float* __restrict__ bias, float* __restrict__ C,
        int M, int Nw, int K, int ldc, int mode){
    __shared__ float As[2][8][128];
    __shared__ float Bs[2][8][128];
    int tid = threadIdx.x;
    int bm = blockIdx.y, bn = blockIdx.x;

    int rowA = tid >> 1;
    int colA = (tid & 1) << 2;
    int rowB = tid >> 5;
    int colB = (tid & 31) << 2;
    int gRowA = bm*128 + rowA;
    int arow_ok = gRowA < M;

    const float* Ab = A + (size_t)gRowA * K + colA;
    const float* Bb = B + (size_t)rowB * Nw + bn*128 + colB;

    float acc[8][8];
    #pragma unroll
    for (int i=0;i<8;i++)
        #pragma unroll
        for (int j=0;j<8;j++) acc[i][j] = 0.f;

    int tr = (tid >> 4) << 3;
    int tc = (tid & 15) << 3;
    int T = K >> 3;

    {
        float4 av = arow_ok ? *(const float4*)Ab : make_float4(0,0,0,0);
        float4 bv = *(const float4*)Bb;
        As[0][colA+0][rowA] = av.x; As[0][colA+1][rowA] = av.y;
        As[0][colA+2][rowA] = av.z; As[0][colA+3][rowA] = av.w;
        *(float4*)&Bs[0][rowB][colB] = bv;
    }
    __syncthreads();

    int p = 0;
    for (int t = 0; t < T; t++){
        float4 av2 = make_float4(0,0,0,0), bv2 = make_float4(0,0,0,0);
        if (t+1 < T){
            if (arow_ok) av2 = *(const float4*)(Ab + (t+1)*8);
            bv2 = *(const float4*)(Bb + (size_t)(t+1)*8*Nw);
        }
        #pragma unroll
        for (int k = 0; k < 8; k++){
            float4 a0 = *(const float4*)&As[p][k][tr];
            float4 a1 = *(const float4*)&As[p][k][tr+4];
            float4 b0 = *(const float4*)&Bs[p][k][tc];
            float4 b1 = *(const float4*)&Bs[p][k][tc+4];
            float ar[8] = {a0.x,a0.y,a0.z,a0.w,a1.x,a1.y,a1.z,a1.w};
            float br[8] = {b0.x,b0.y,b0.z,b0.w,b1.x,b1.y,b1.z,b1.w};
            #pragma unroll
            for (int i=0;i<8;i++)
                #pragma unroll
                for (int j=0;j<8;j++) acc[i][j] += ar[i]*br[j];
        }
        if (t+1 < T){
            int q = p ^ 1;
            As[q][colA+0][rowA] = av2.x; As[q][colA+1][rowA] = av2.y;
            As[q][colA+2][rowA] = av2.z; As[q][colA+3][rowA] = av2.w;
            *(float4*)&Bs[q][rowB][colB] = bv2;
            __syncthreads();
            p = q;
        }
    }

    #pragma unroll
    for (int i = 0; i < 8; i++){
        int row = bm*128 + tr + i;
        if (row >= M) break;
        #pragma unroll
        for (int j = 0; j < 8; j += 4){
            int col = bn*128 + tc + j;
            float b0 = bias ? bias[col+0] : 0.f;
            float b1 = bias ? bias[col+1] : 0.f;
            float b2 = bias ? bias[col+2] : 0.f;
            float b3 = bias ? bias[col+3] : 0.f;
            float4 o;
            o.x = acc[i][j+0] + b0;
            o.y = acc[i][j+1] + b1;
            o.z = acc[i][j+2] + b2;
            o.w = acc[i][j+3] + b3;
            if (mode == 1){
                o.x = fmaxf(o.x,0.f); o.y = fmaxf(o.y,0.f);
                o.z = fmaxf(o.z,0.f); o.w = fmaxf(o.w,0.f);
                *(float4*)&C[(size_t)row*ldc + col] = o;
            } else if (mode == 2){
                // xcat[:,128+col] = relu(gated seg) * sigmoid(twin)
                bool has = g_cnts[row] > 0.f;
                float4 sg = *(const float4*)&g_seg[(size_t)row*128 + col];
                float s0 = has ? fmaxf(sg.x, 0.f) : 0.f;
                float s1 = has ? fmaxf(sg.y, 0.f) : 0.f;
                float s2 = has ? fmaxf(sg.z, 0.f) : 0.f;
                float s3 = has ? fmaxf(sg.w, 0.f) : 0.f;
                float4 w;
                w.x = s0 / (1.f + __expf(-o.x));
                w.y = s1 / (1.f + __expf(-o.y));
                w.z = s2 / (1.f + __expf(-o.z));
                w.w = s3 / (1.f + __expf(-o.w));
                *(float4*)&C[(size_t)row*ldc + 128 + col] = w;
            } else {
                *(float4*)&C[(size_t)row*ldc + col] = o;
            }
        }
    }
}

// ---------------- attention: MLP (head-amortized) + softmax + scatter-max ----------------
__global__ __launch_bounds__(256) void attention_kernel(
        const int* __restrict__ src, const int* __restrict__ dst,
        const float* __restrict__ A1, const float* __restrict__ a1,
        const float* __restrict__ A2, const float* __restrict__ a2,
        int E){
    __shared__ float sA1t[64*64];
    __shared__ float sA2t[64*32];
    __shared__ float sa1[64], sa2[32];
    __shared__ float qe_s[4][256];
    __shared__ float v_s[4][128];
    __shared__ float h1_s[4][256];
    int t = threadIdx.x;
    for (int i = t; i < 4096; i += 256){ int o = i >> 6, c = i & 63; sA1t[c*64 + o] = A1[i]; }
    for (int i = t; i < 2048; i += 256){ int o = i >> 6, c = i & 63; sA2t[c*32 + o] = A2[i]; }
    if (t < 64) sa1[t] = a1[t];
    if (t < 32) sa2[t] = a2[t];
    __syncthreads();

    int slot = t >> 6;
    int o    = t & 63;

    for (long long e0 = (long long)blockIdx.x*4; e0 < E; e0 += (long long)gridDim.x*4){
        long long e = e0 + slot;
        bool ok = (e < E);
        int s = 0, d = 0;
        if (ok){ s = src[e]; d = dst[e]; }
        if (ok){
            if (o < 32){
                ((float4*)qe_s[slot])[o] = ((const float4*)(g_qv + (size_t)s*256))[o];
                ((float4*)v_s[slot])[o]  = ((const float4*)(g_qv + (size_t)d*256 + 128))[o];
            } else {
                ((float4*)qe_s[slot])[o] = ((const float4*)(g_PP + e*PPW + 768))[o-32];
            }
        }
        __syncthreads();

        float b1 = sa1[o];
        float c0 = b1, c1 = b1, c2 = b1, c3 = b1;
        #pragma unroll 8
        for (int c = 0; c < 64; c++){
            float w = sA1t[c*64 + o];
            float4 in = *(const float4*)&qe_s[slot][c*4];
            c0 += w*in.x; c1 += w*in.y; c2 += w*in.z; c3 += w*in.w;
        }
        float4 h1v = make_float4(fmaxf(c0,0.f), fmaxf(c1,0.f), fmaxf(c2,0.f), fmaxf(c3,0.f));
        *(float4*)&h1_s[slot][o*4] = h1v;
        __syncthreads();

        if (o < 32){
            float b2 = sa2[o];
            float p0 = b2, p1 = b2, p2 = b2, p3 = b2;
            #pragma unroll 8
            for (int c = 0; c < 64; c++){
                float w = sA2t[c*32 + o];
                float4 in = *(const float4*)&h1_s[slot][c*4];
                p0 += w*in.x; p1 += w*in.y; p2 += w*in.z; p3 += w*in.w;
            }
            if (ok){
                float vals[4] = {p0, p1, p2, p3};
                float4 vv = *(const float4*)&v_s[slot][o*4];
                float vvv[4] = {vv.x, vv.y, vv.z, vv.w};
                #pragma unroll
                for (int h = 0; h < 4; h++){
                    float m = vals[h];
                    #pragma unroll
                    for (int off = 16; off; off >>= 1)
                        m = fmaxf(m, __shfl_xor_sync(0xffffffffu, m, off));
                    float ex = __expf(vals[h] - m);
                    float sm = ex;
                    #pragma unroll
                    for (int off = 16; off; off >>= 1)
                        sm += __shfl_xor_sync(0xffffffffu, sm, off);
                    float prob = ex / sm;
                    atomicMaxF(&g_seg[(size_t)s*128 + o*4 + h], prob * vvv[h]);
                }
            }
        }
        __syncthreads();
    }
}

// ---------------- node-side glue ----------------
__global__ void build_twin_in(const float* __restrict__ x, int N){
    int i = blockIdx.x*blockDim.x + threadIdx.x;
    if (i >= N*128) return;
    int n = i >> 7, c = i & 127;
    g_twin_in[(size_t)n*256 + c]       = g_subj[i] / fmaxf(g_cnts[n], 1.f);
    g_twin_in[(size_t)n*256 + 128 + c] = g_obj[i]  / fmaxf(g_cntd[n], 1.f);
    g_xcat[(size_t)n*256 + c] = x[i];
}

// ---------------- final LayerNorm ----------------
__global__ __launch_bounds__(256) void ln_final(
        const float* __restrict__ gn, const float* __restrict__ bn,
        float* __restrict__ out_x, int N){
    int n = blockIdx.x * 8 + (threadIdx.x >> 5);
    if (n >= N) return;
    int lane = threadIdx.x & 31;
    const float* row = g_ptmp + (size_t)n*128;
    float4 v = *(const float4*)&row[lane*4];
    float s  = v.x + v.y + v.z + v.w;
    float ss = v.x*v.x + v.y*v.y + v.z*v.z + v.w*v.w;
    #pragma unroll
    for (int off = 16; off; off >>= 1){
        s  += __shfl_xor_sync(0xffffffffu, s,  off);
        ss += __shfl_xor_sync(0xffffffffu, ss, off);
    }
    float mean = s * (1.f/128.f);
    float var  = ss * (1.f/128.f) - mean*mean;
    float rstd = rsqrtf(var + 1e-5f);
    float vv[4] = {v.x, v.y, v.z, v.w};
    #pragma unroll
    for (int q = 0; q < 4; q++){
        int c = lane*4 + q;
        out_x[(size_t)n*128 + c] = (vv[q] - mean) * rstd * gn[c] + bn[c];
    }
}

// ---------------- host ----------------
extern "C" void kernel_launch(void* const* d_in, const int* in_sizes, int n_in,
                              void* d_out, int out_size){
    const float* x    = (const float*)d_in[0];
    const float* ef   = (const float*)d_in[1];
    const int*   eidx = (const int*)  d_in[2];
    const float* Wg1  = (const float*)d_in[3];
    const float* bg1  = (const float*)d_in[4];
    const float* Wg2  = (const float*)d_in[5];
    const float* bg2  = (const float*)d_in[6];
    const float* We1  = (const float*)d_in[7];
    const float* be1  = (const float*)d_in[8];
    const float* We2  = (const float*)d_in[9];
    const float* be2  = (const float*)d_in[10];
    const float* ge   = (const float*)d_in[11];
    const float* beta_e=(const float*)d_in[12];
    const float* Wq   = (const float*)d_in[13];
    const float* bq   = (const float*)d_in[14];
    const float* Wpe  = (const float*)d_in[15];
    const float* bpe  = (const float*)d_in[16];
    const float* Wv   = (const float*)d_in[17];
    const float* bv   = (const float*)d_in[18];
    const float* A1   = (const float*)d_in[19];
    const float* a1   = (const float*)d_in[20];
    const float* A2   = (const float*)d_in[21];
    const float* a2   = (const float*)d_in[22];
    const float* Wt   = (const float*)d_in[23];
    const float* bt   = (const float*)d_in[24];
    const float* Wp1  = (const float*)d_in[25];
    const float* bp1  = (const float*)d_in[26];
    const float* Wp2  = (const float*)d_in[27];
    const float* bp2  = (const float*)d_in[28];
    const float* gn   = (const float*)d_in[29];
    const float* bn   = (const float*)d_in[30];

    int N = in_sizes[0] / 128;
    int E = in_sizes[2] / 2;
    const int* src = eidx;
    const int* dst = eidx + E;

    float* out_x = (float*)d_out;                        // [N,128]
    float* out_e = (float*)d_out + (size_t)N * 128;      // [E,128]

    float *pPP, *pXX, *pQV, *pTIN, *pXCAT, *pPH, *pPTMP;
    float *pBpE, *pBpN, *pBias, *pWqv, *pbqv;
    cudaGetSymbolAddress((void**)&pPP,   g_PP);
    cudaGetSymbolAddress((void**)&pXX,   g_XX);
    cudaGetSymbolAddress((void**)&pQV,   g_qv);
    cudaGetSymbolAddress((void**)&pTIN,  g_twin_in);
    cudaGetSymbolAddress((void**)&pXCAT, g_xcat);
    cudaGetSymbolAddress((void**)&pPH,   g_ph);
    cudaGetSymbolAddress((void**)&pPTMP, g_ptmp);
    cudaGetSymbolAddress((void**)&pBpE,  g_BpE);
    cudaGetSymbolAddress((void**)&pBpN,  g_BpN);
    cudaGetSymbolAddress((void**)&pBias, g_biasPP);
    cudaGetSymbolAddress((void**)&pWqv,  g_Wqv);
    cudaGetSymbolAddress((void**)&pbqv,  g_bqv);

    // 1) init state
    init_kernel<<<2048, 256>>>(N);
    // 2) repack weights
    repack_We1<<<(128*PPW + 255)/256, 256>>>(We1, Wpe, Wg1);
    repack_BpN_bias<<<(128*768 + 255)/256, 256>>>(We1, bpe, bg1);
    repack_qv<<<(128*256 + 255)/256, 256>>>(Wq, bq, Wv, bv);
    // 3) hash insert + degree counts
    hash_insert<<<(E + 255)/256, 256>>>(src, dst, E, N);
    // 4) reverse lookup
    rev_lookup<<<(E + 255)/256, 256>>>(src, dst, E, N);
    // 5) node part of nn_edge layer1: XX = x @ BpN   [N,768] (fp32)
    { dim3 g(768/128, (N+127)/128); sgemm128<<<g,256>>>(x, pBpN, 0, pXX, N, 768, 128, 768, 0); }
    // 6) big edge GEMM (TF32) with fused gate epilogue on bn=7
    { dim3 g(PPW/128, (E+127)/128);
      tgemm_pp<<<g,256>>>(ef, pBpE, pBias, pPP, E, PPW, 128, 7, Wg2, bg2); }
    // 7) fused: build_h1 + h1@We2+be2 + LN + subj/obj scatter -> out_e
    edge_mlp2_ln<<<(E + 127)/128, 256>>>(src, dst, We2, be1, be2, ge, beta_e, out_e, E);
    // 8) fused q|v projection [N,256]
    { dim3 g(2, (N+127)/128); sgemm128<<<g,256>>>(x, pWqv, pbqv, pQV, N, 256, 128, 256, 0); }
    // 9) attention + scatter-max
    attention_kernel<<<8192, 256>>>(src, dst, A1, a1, A2, a2, E);
    // 10) twin input (segment means) + xcat[:,0:128] = x
    build_twin_in<<<(N*128 + 255)/256, 256>>>(x, N);
    // 11) twin GEMM with fused xcat epilogue -> xcat[:,128:256]
    { dim3 g(1, (N+127)/128); sgemm128<<<g,256>>>(pTIN, Wt, bt, pXCAT, N, 128, 256, 256, 2); }
    // 12) ph = relu(xcat @ Wp1 + bp1)
    { dim3 g(2, (N+127)/128); sgemm128<<<g,256>>>(pXCAT, Wp1, bp1, pPH, N, 256, 256, 256, 1); }
    // 13) ptmp = ph @ Wp2 + bp2
    { dim3 g(1, (N+127)/128); sgemm128<<<g,256>>>(pPH, Wp2, bp2, pPTMP, N, 128, 256, 128, 0); }
    // 14) final LN -> out_x
    ln_final<<<(N + 7)/8, 256>>>(gn, bn, out_x, N);
}

// round 8
// speedup vs baseline: 3.1816x; 1.2802x over previous
#include <cuda_runtime.h>
#include <math.h>

#define EMAX 320000
#define NMAX 10000
#define HS   (1<<20)
#define PPW  1024   // PP stride: [We1_e 384 | We1_rev 384 | Wpe 128 | gate-hidden 64 | pad 64]
#define INIT_LIMIT ((long long)(NMAX)*128 > (long long)HS ? (long long)(NMAX)*128 : (long long)HS)

// ---------------- scratch ----------------
__device__ long long g_hkey[HS];
__device__ int       g_hval[HS];
__device__ float g_gates[EMAX];
__device__ int   g_rev[EMAX];
__device__ float g_PP[(long long)EMAX*PPW];
__device__ float g_XX[NMAX*768];
__device__ float g_qv[NMAX*256];
__device__ float g_seg[NMAX*128];
__device__ float g_subj[NMAX*128];
__device__ float g_obj[NMAX*128];
__device__ float g_cnts[NMAX];
__device__ float g_cntd[NMAX];
__device__ float g_twin_in[NMAX*256];
__device__ float g_xcat[NMAX*256];
__device__ float g_ph[NMAX*256];
__device__ float g_ptmp[NMAX*128];
__device__ float g_BpE[128*PPW];
__device__ float g_BpN[128*768];
__device__ float g_Wqv[128*256];
__device__ float g_bqv[256];
__device__ float g_biasPP[PPW];

// ---------------- helpers ----------------
__device__ __forceinline__ unsigned hash64(long long k){
    unsigned long long z = (unsigned long long)k;
    z *= 0x9E3779B97F4A7C15ull;
    z ^= z >> 29; z *= 0xBF58476D1CE4E5B9ull; z ^= z >> 32;
    return (unsigned)z;
}

__device__ __forceinline__ void atomicMaxF(float* addr, float v){
    if (v >= 0.f) atomicMax((int*)addr, __float_as_int(v));
    else          atomicMin((unsigned int*)addr, __float_as_uint(v));
}

__device__ __forceinline__ void red2(float* p, float a, float b){
    asm volatile("red.global.add.v2.f32 [%0], {%1, %2};" :: "l"(p), "f"(a), "f"(b) : "memory");
}

__device__ __forceinline__ unsigned f2tf(float f){
    unsigned u;
    asm("cvt.rna.tf32.f32 %0, %1;" : "=r"(u) : "f"(f));
    return u;
}

#define MMA_TF32(c, a0,a1,a2,a3, b0,b1) \
    asm volatile("mma.sync.aligned.m16n8k8.row.col.f32.tf32.tf32.f32 " \
        "{%0,%1,%2,%3}, {%4,%5,%6,%7}, {%8,%9}, {%0,%1,%2,%3};" \
        : "+f"((c)[0]),"+f"((c)[1]),"+f"((c)[2]),"+f"((c)[3]) \
        : "r"(a0),"r"(a1),"r"(a2),"r"(a3),"r"(b0),"r"(b1))

// ---------------- init ----------------
__global__ void init_kernel(int N){
    long long stride = (long long)gridDim.x * blockDim.x;
    long long limit = INIT_LIMIT;
    for (long long i = (long long)blockIdx.x*blockDim.x + threadIdx.x; i < limit; i += stride){
        if (i < HS){
            g_hkey[i] = -1LL;
            g_hval[i] = 0x7fffffff;
        }
        if (i < (long long)N*128){
            g_seg[i]  = __int_as_float(0xff800000); // -inf
            g_subj[i] = 0.f;
            g_obj[i]  = 0.f;
        }
        if (i < N){ g_cnts[i] = 0.f; g_cntd[i] = 0.f; }
    }
}

// ---------------- repacks ----------------
__global__ void repack_We1(const float* __restrict__ We1,
                           const float* __restrict__ Wpe,
                           const float* __restrict__ Wg1){
    int i = blockIdx.x*blockDim.x + threadIdx.x;
    if (i >= 128*PPW) return;
    int k = i / PPW, j = i % PPW;
    float v;
    if      (j < 384)  v = We1[(128+k)*384 + j];
    else if (j < 768)  v = We1[(256+k)*384 + (j-384)];
    else if (j < 896)  v = Wpe[k*128 + (j-768)];
    else if (j < 960)  v = Wg1[k*64 + (j-896)];
    else               v = 0.f;
    g_BpE[i] = v;
}

__global__ void repack_BpN_bias(const float* __restrict__ We1,
                                const float* __restrict__ bpe,
                                const float* __restrict__ bg1){
    int i = blockIdx.x*blockDim.x + threadIdx.x;
    if (i < 128*768){
        int k = i / 768, j = i % 768;
        g_BpN[i] = (j < 384) ? We1[k*384 + j] : We1[(384+k)*384 + (j-384)];
    }
    if (i < PPW){
        float v = 0.f;
        if      (i >= 768 && i < 896) v = bpe[i-768];
        else if (i >= 896 && i < 960) v = bg1[i-896];
        g_biasPP[i] = v;
    }
}

__global__ void repack_qv(const float* __restrict__ Wq, const float* __restrict__ bq,
                          const float* __restrict__ Wv, const float* __restrict__ bv){
    int i = blockIdx.x*blockDim.x + threadIdx.x;
    if (i < 128*256){
        int k = i / 256, j = i % 256;
        g_Wqv[i] = (j < 128) ? Wq[k*128 + j] : Wv[k*128 + (j-128)];
    }
    if (i < 256) g_bqv[i] = (i < 128) ? bq[i] : bv[i-128];
}

// ---------------- hash insert (+ degree counts) ----------------
__global__ void hash_insert(const int* __restrict__ src, const int* __restrict__ dst,
                            int E, int N){
    int e = blockIdx.x*blockDim.x + threadIdx.x;
    if (e >= E) return;
    int s = src[e], d = dst[e];
    long long key = (long long)s * N + d;
    unsigned slot = hash64(key) & (HS-1);
    for (;;){
        unsigned long long prev = atomicCAS((unsigned long long*)&g_hkey[slot],
                                            0xFFFFFFFFFFFFFFFFull,
                                            (unsigned long long)key);
        if (prev == 0xFFFFFFFFFFFFFFFFull || (long long)prev == key){
            atomicMin(&g_hval[slot], e);
            break;
        }
        slot = (slot + 1) & (HS-1);
    }
    atomicAdd(&g_cnts[s], 1.f);
    atomicAdd(&g_cntd[d], 1.f);
}

// ---------------- reverse-edge lookup ----------------
__global__ void rev_lookup(const int* __restrict__ src, const int* __restrict__ dst,
                           int E, int N){
    int e = blockIdx.x*blockDim.x + threadIdx.x;
    if (e >= E) return;
    long long rkey = (long long)dst[e] * N + src[e];
    unsigned slot = hash64(rkey) & (HS-1);
    int r = -1;
    for (;;){
        long long k = g_hkey[slot];
        if (k == -1LL) break;
        if (k == rkey){ r = g_hval[slot]; break; }
        slot = (slot + 1) & (HS-1);
    }
    g_rev[e] = r;
}

// ---------------- TF32 GEMM for PP with fused gate epilogue ----------------
__global__ __launch_bounds__(256, 2) void tgemm_pp(
        const float* __restrict__ A, const float* __restrict__ B,
        const float* __restrict__ bias, float* __restrict__ C,
        int M, int Nw, int K, int gate_bn,
        const float* __restrict__ Wg2, const float* __restrict__ bg2){
    __shared__ unsigned As[128][36];
    __shared__ unsigned Bs[32][136];
    __shared__ float gpart[128];

    int tid  = threadIdx.x;
    int lane = tid & 31, wid = tid >> 5;
    int warp_m = wid >> 2, warp_n = wid & 3;
    int grp = lane >> 2, tig = lane & 3;
    int bm = blockIdx.y, bn = blockIdx.x;

    if (tid < 128) gpart[tid] = 0.f;

    int arow = tid >> 3;
    int acol = (tid & 7) << 2;
    int brow0 = tid >> 5;
    int bcol  = (tid & 31) << 2;

    float acc[4][4][4];
    #pragma unroll
    for (int i=0;i<4;i++)
        #pragma unroll
        for (int j=0;j<4;j++)
            #pragma unroll
            for (int r=0;r<4;r++) acc[i][j][r] = 0.f;

    int T = K >> 5;
    float4 apf[4], bpf[4];

    {
        #pragma unroll
        for (int r = 0; r < 4; r++){
            int grow = bm*128 + arow + r*32;
            apf[r] = (grow < M) ? *(const float4*)(A + (size_t)grow*K + acol)
                                : make_float4(0,0,0,0);
        }
        #pragma unroll
        for (int r = 0; r < 4; r++){
            int gk = brow0 + r*8;
            bpf[r] = *(const float4*)(B + (size_t)gk*Nw + bn*128 + bcol);
        }
    }

    for (int t = 0; t < T; t++){
        #pragma unroll
        for (int r = 0; r < 4; r++){
            unsigned* d = &As[arow + r*32][acol];
            d[0] = f2tf(apf[r].x); d[1] = f2tf(apf[r].y);
            d[2] = f2tf(apf[r].z); d[3] = f2tf(apf[r].w);
        }
        #pragma unroll
        for (int r = 0; r < 4; r++){
            unsigned* d = &Bs[brow0 + r*8][bcol];
            d[0] = f2tf(bpf[r].x); d[1] = f2tf(bpf[r].y);
            d[2] = f2tf(bpf[r].z); d[3] = f2tf(bpf[r].w);
        }
        __syncthreads();

        if (t+1 < T){
            int koff = (t+1) << 5;
            #pragma unroll
            for (int r = 0; r < 4; r++){
                int grow = bm*128 + arow + r*32;
                apf[r] = (grow < M) ? *(const float4*)(A + (size_t)grow*K + koff + acol)
                                    : make_float4(0,0,0,0);
            }
            #pragma unroll
            for (int r = 0; r < 4; r++){
                int gk = koff + brow0 + r*8;
                bpf[r] = *(const float4*)(B + (size_t)gk*Nw + bn*128 + bcol);
            }
        }

        #pragma unroll
        for (int ks = 0; ks < 4; ks++){
            int kc = (ks << 3) + tig;
            unsigned a[4][4], b[4][2];
            #pragma unroll
            for (int mt = 0; mt < 4; mt++){
                int rb = warp_m*64 + mt*16 + grp;
                a[mt][0] = As[rb][kc];
                a[mt][1] = As[rb+8][kc];
                a[mt][2] = As[rb][kc+4];
                a[mt][3] = As[rb+8][kc+4];
            }
            #pragma unroll
            for (int nt = 0; nt < 4; nt++){
                int cb = warp_n*32 + nt*8 + grp;
                b[nt][0] = Bs[(ks<<3) + tig][cb];
                b[nt][1] = Bs[(ks<<3) + tig + 4][cb];
            }
            #pragma unroll
            for (int mt = 0; mt < 4; mt++)
                #pragma unroll
                for (int nt = 0; nt < 4; nt++)
                    MMA_TF32(acc[mt][nt], a[mt][0],a[mt][1],a[mt][2],a[mt][3],
                             b[nt][0], b[nt][1]);
        }
        __syncthreads();
    }

    if (bn == gate_bn){
        #pragma unroll
        for (int mt = 0; mt < 4; mt++){
            float pa = 0.f, pb = 0.f;
            #pragma unroll
            for (int nt = 0; nt < 4; nt++){
                int lc = warp_n*32 + nt*8 + tig*2;
                if (lc < 64){
                    float w0 = __ldg(&Wg2[lc]);
                    float w1 = __ldg(&Wg2[lc+1]);
                    float b0 = __ldg(&bias[bn*128 + lc]);
                    float b1 = __ldg(&bias[bn*128 + lc + 1]);
                    pa += fmaxf(acc[mt][nt][0]+b0, 0.f)*w0 + fmaxf(acc[mt][nt][1]+b1, 0.f)*w1;
                    pb += fmaxf(acc[mt][nt][2]+b0, 0.f)*w0 + fmaxf(acc[mt][nt][3]+b1, 0.f)*w1;
                }
            }
            pa += __shfl_xor_sync(0xffffffffu, pa, 1);
            pa += __shfl_xor_sync(0xffffffffu, pa, 2);
            pb += __shfl_xor_sync(0xffffffffu, pb, 1);
            pb += __shfl_xor_sync(0xffffffffu, pb, 2);
            if (tig == 0){
                int ra = warp_m*64 + mt*16 + grp;
                atomicAdd(&gpart[ra], pa);
                atomicAdd(&gpart[ra+8], pb);
            }
        }
        __syncthreads();
        if (tid < 128){
            int e = bm*128 + tid;
            if (e < M)
                g_gates[e] = 1.f / (1.f + __expf(-(gpart[tid] + bg2[0])));
        }
    } else {
        #pragma unroll
        for (int mt = 0; mt < 4; mt++){
            int row0 = bm*128 + warp_m*64 + mt*16 + grp;
            #pragma unroll
            for (int nt = 0; nt < 4; nt++){
                int col = bn*128 + warp_n*32 + nt*8 + tig*2;
                float b0 = __ldg(&bias[col]);
                float b1 = __ldg(&bias[col+1]);
                if (row0 < M)
                    *(float2*)&C[(size_t)row0*Nw + col] =
                        make_float2(acc[mt][nt][0]+b0, acc[mt][nt][1]+b1);
                if (row0+8 < M)
                    *(float2*)&C[(size_t)(row0+8)*Nw + col] =
                        make_float2(acc[mt][nt][2]+b0, acc[mt][nt][3]+b1);
            }
        }
    }
}

// ---------------- fused: build_h1 + (h1@We2+be2) + LayerNorm + subj/obj scatter ----------------
__global__ __launch_bounds__(256, 2) void edge_mlp2_ln(
        const int* __restrict__ src, const int* __restrict__ dst,
        const float* __restrict__ We2, const float* __restrict__ be1,
        const float* __restrict__ be2,
        const float* __restrict__ ge, const float* __restrict__ beta_e,
        float* __restrict__ out_edge, int E){
    __shared__ unsigned As[128][36];
    __shared__ unsigned Bs[32][136];
    __shared__ int   s_s[128], s_d[128], s_r[128];
    __shared__ float s_g[128];
    __shared__ float s_be2[128], s_ge[128], s_be[128];
    __shared__ float s_sum[128], s_sq[128];
    __shared__ float s_mean[128], s_rstd[128];

    int tid  = threadIdx.x;
    int lane = tid & 31, wid = tid >> 5;
    int warp_m = wid >> 2, warp_n = wid & 3;
    int grp = lane >> 2, tig = lane & 3;
    long long e0 = (long long)blockIdx.x * 128;

    if (tid < 128){
        long long e = e0 + tid;
        int s = 0, d = 0, r = -1; float g = 0.f;
        if (e < E){ s = src[e]; d = dst[e]; r = g_rev[e]; g = g_gates[e]; }
        s_s[tid] = s; s_d[tid] = d; s_r[tid] = r; s_g[tid] = g;
        s_be2[tid] = be2[tid]; s_ge[tid] = ge[tid]; s_be[tid] = beta_e[tid];
        s_sum[tid] = 0.f; s_sq[tid] = 0.f;
    }
    __syncthreads();

    int arow = tid >> 3;
    int acol = (tid & 7) << 2;
    int brow0 = tid >> 5;
    int bcol  = (tid & 31) << 2;

    float acc[4][4][4];
    #pragma unroll
    for (int i=0;i<4;i++)
        #pragma unroll
        for (int j=0;j<4;j++)
            #pragma unroll
            for (int r=0;r<4;r++) acc[i][j][r] = 0.f;

    const int T = 12;   // 384/32
    float4 apf[4], bpf[4];

    #define LOAD_A_TILE(koff) { \
        _Pragma("unroll") \
        for (int r = 0; r < 4; r++){ \
            int row = arow + r*32; \
            int j = (koff) + acol; \
            long long e = e0 + row; if (e >= E) e = E-1; \
            float4 pp = *(const float4*)(g_PP + (size_t)e*PPW + j); \
            float4 xs = *(const float4*)(g_XX + (size_t)s_s[row]*768 + j); \
            float4 xd = *(const float4*)(g_XX + (size_t)s_d[row]*768 + 384 + j); \
            float4 b1 = *(const float4*)(be1 + j); \
            int rv = s_r[row]; float g = s_g[row]; \
            float4 pr = make_float4(0,0,0,0); \
            if (rv >= 0) pr = *(const float4*)(g_PP + (size_t)rv*PPW + 384 + j); \
            apf[r].x = fmaxf(b1.x + xs.x + pp.x + xd.x + g*pr.x, 0.f); \
            apf[r].y = fmaxf(b1.y + xs.y + pp.y + xd.y + g*pr.y, 0.f); \
            apf[r].z = fmaxf(b1.z + xs.z + pp.z + xd.z + g*pr.z, 0.f); \
            apf[r].w = fmaxf(b1.w + xs.w + pp.w + xd.w + g*pr.w, 0.f); \
        } \
    }
    #define LOAD_B_TILE(koff) { \
        _Pragma("unroll") \
        for (int r = 0; r < 4; r++){ \
            int gk = (koff) + brow0 + r*8; \
            bpf[r] = *(const float4*)(We2 + (size_t)gk*128 + bcol); \
        } \
    }

    LOAD_A_TILE(0);
    LOAD_B_TILE(0);

    for (int t = 0; t < T; t++){
        #pragma unroll
        for (int r = 0; r < 4; r++){
            unsigned* dp = &As[arow + r*32][acol];
            dp[0] = f2tf(apf[r].x); dp[1] = f2tf(apf[r].y);
            dp[2] = f2tf(apf[r].z); dp[3] = f2tf(apf[r].w);
        }
        #pragma unroll
        for (int r = 0; r < 4; r++){
            unsigned* dp = &Bs[brow0 + r*8][bcol];
            dp[0] = f2tf(bpf[r].x); dp[1] = f2tf(bpf[r].y);
            dp[2] = f2tf(bpf[r].z); dp[3] = f2tf(bpf[r].w);
        }
        __syncthreads();

        if (t+1 < T){
            int koff = (t+1) << 5;
            LOAD_A_TILE(koff);
            LOAD_B_TILE(koff);
        }

        #pragma unroll
        for (int ks = 0; ks < 4; ks++){
            int kc = (ks << 3) + tig;
            unsigned a[4][4], b[4][2];
            #pragma unroll
            for (int mt = 0; mt < 4; mt++){
                int rb = warp_m*64 + mt*16 + grp;
                a[mt][0] = As[rb][kc];
                a[mt][1] = As[rb+8][kc];
                a[mt][2] = As[rb][kc+4];
                a[mt][3] = As[rb+8][kc+4];
            }
            #pragma unroll
            for (int nt = 0; nt < 4; nt++){
                int cb = warp_n*32 + nt*8 + grp;
                b[nt][0] = Bs[(ks<<3) + tig][cb];
                b[nt][1] = Bs[(ks<<3) + tig + 4][cb];
            }
            #pragma unroll
            for (int mt = 0; mt < 4; mt++)
                #pragma unroll
                for (int nt = 0; nt < 4; nt++)
                    MMA_TF32(acc[mt][nt], a[mt][0],a[mt][1],a[mt][2],a[mt][3],
                             b[nt][0], b[nt][1]);
        }
        __syncthreads();
    }

    #pragma unroll
    for (int mt = 0; mt < 4; mt++){
        float pas = 0.f, paq = 0.f, pbs = 0.f, pbq = 0.f;
        #pragma unroll
        for (int nt = 0; nt < 4; nt++){
            int col = warp_n*32 + nt*8 + tig*2;
            float b0 = s_be2[col], b1 = s_be2[col+1];
            acc[mt][nt][0] += b0; acc[mt][nt][1] += b1;
            acc[mt][nt][2] += b0; acc[mt][nt][3] += b1;
            pas += acc[mt][nt][0] + acc[mt][nt][1];
            paq += acc[mt][nt][0]*acc[mt][nt][0] + acc[mt][nt][1]*acc[mt][nt][1];
            pbs += acc[mt][nt][2] + acc[mt][nt][3];
            pbq += acc[mt][nt][2]*acc[mt][nt][2] + acc[mt][nt][3]*acc[mt][nt][3];
        }
        pas += __shfl_xor_sync(0xffffffffu, pas, 1);
        pas += __shfl_xor_sync(0xffffffffu, pas, 2);
        paq += __shfl_xor_sync(0xffffffffu, paq, 1);
        paq += __shfl_xor_sync(0xffffffffu, paq, 2);
        pbs += __shfl_xor_sync(0xffffffffu, pbs, 1);
        pbs += __shfl_xor_sync(0xffffffffu, pbs, 2);
        pbq += __shfl_xor_sync(0xffffffffu, pbq, 1);
        pbq += __shfl_xor_sync(0xffffffffu, pbq, 2);
        if (tig == 0){
            int ra = warp_m*64 + mt*16 + grp;
            atomicAdd(&s_sum[ra],   pas);
            atomicAdd(&s_sq[ra],    paq);
            atomicAdd(&s_sum[ra+8], pbs);
            atomicAdd(&s_sq[ra+8],  pbq);
        }
    }
    __syncthreads();
    if (tid < 128){
        float m = s_sum[tid] * (1.f/128.f);
        float v = s_sq[tid] * (1.f/128.f) - m*m;
        s_mean[tid] = m;
        s_rstd[tid] = rsqrtf(v + 1e-5f);
    }
    __syncthreads();

    #pragma unroll
    for (int mt = 0; mt < 4; mt++){
        int ra = warp_m*64 + mt*16 + grp;
        int rb = ra + 8;
        long long ea = e0 + ra, eb = e0 + rb;
        float ma = s_mean[ra], rsa = s_rstd[ra];
        float mb = s_mean[rb], rsb = s_rstd[rb];
        int sa = s_s[ra], da = s_d[ra];
        int sb = s_s[rb], db = s_d[rb];
        #pragma unroll
        for (int nt = 0; nt < 4; nt++){
            int col = warp_n*32 + nt*8 + tig*2;
            float gsc0 = s_ge[col], gsc1 = s_ge[col+1];
            float bsc0 = s_be[col], bsc1 = s_be[col+1];
            if (ea < E){
                float o0 = (acc[mt][nt][0]-ma)*rsa*gsc0 + bsc0;
                float o1 = (acc[mt][nt][1]-ma)*rsa*gsc1 + bsc1;
                *(float2*)&out_edge[ea*128 + col] = make_float2(o0, o1);
                red2(&g_subj[(size_t)sa*128 + col], o0, o1);
                red2(&g_obj [(size_t)da*128 + col], o0, o1);
            }
            if (eb < E){
                float o2 = (acc[mt][nt][2]-mb)*rsb*gsc0 + bsc0;
                float o3 = (acc[mt][nt][3]-mb)*rsb*gsc1 + bsc1;
                *(float2*)&out_edge[eb*128 + col] = make_float2(o2, o3);
                red2(&g_subj[(size_t)sb*128 + col], o2, o3);
                red2(&g_obj [(size_t)db*128 + col], o2, o3);
            }
        }
    }
}

// ---------------- fp32 SGEMM (node-sized) with epilogue modes ----------------
__global__ __launch_bounds__(256) void sgemm128(
        const float* __restrict__ A, const float* __restrict__ B,
        const float* __restrict__ bias, float* __restrict__ C,
        int M, int Nw, int K, int ldc, int mode){
    __shared__ float As[2][8][128];
    __shared__ float Bs[2][8][128];
    int tid = threadIdx.x;
    int bm = blockIdx.y, bn = blockIdx.x;

    int rowA = tid >> 1;
    int colA = (tid & 1) << 2;
    int rowB = tid >> 5;
    int colB = (tid & 31) << 2;
    int gRowA = bm*128 + rowA;
    int arow_ok = gRowA < M;

    const float* Ab = A + (size_t)gRowA * K + colA;
    const float* Bb = B + (size_t)rowB * Nw + bn*128 + colB;

    float acc[8][8];
    #pragma unroll
    for (int i=0;i<8;i++)
        #pragma unroll
        for (int j=0;j<8;j++) acc[i][j] = 0.f;

    int tr = (tid >> 4) << 3;
    int tc = (tid & 15) << 3;
    int T = K >> 3;

    {
        float4 av = arow_ok ? *(const float4*)Ab : make_float4(0,0,0,0);
        float4 bv = *(const float4*)Bb;
        As[0][colA+0][rowA] = av.x; As[0][colA+1][rowA] = av.y;
        As[0][colA+2][rowA] = av.z; As[0][colA+3][rowA] = av.w;
        *(float4*)&Bs[0][rowB][colB] = bv;
    }
    __syncthreads();

    int p = 0;
    for (int t = 0; t < T; t++){
        float4 av2 = make_float4(0,0,0,0), bv2 = make_float4(0,0,0,0);
        if (t+1 < T){
            if (arow_ok) av2 = *(const float4*)(Ab + (t+1)*8);
            bv2 = *(const float4*)(Bb + (size_t)(t+1)*8*Nw);
        }
        #pragma unroll
        for (int k = 0; k < 8; k++){
            float4 a0 = *(const float4*)&As[p][k][tr];
            float4 a1 = *(const float4*)&As[p][k][tr+4];
            float4 b0 = *(const float4*)&Bs[p][k][tc];
            float4 b1 = *(const float4*)&Bs[p][k][tc+4];
            float ar[8] = {a0.x,a0.y,a0.z,a0.w,a1.x,a1.y,a1.z,a1.w};
            float br[8] = {b0.x,b0.y,b0.z,b0.w,b1.x,b1.y,b1.z,b1.w};
            #pragma unroll
            for (int i=0;i<8;i++)
                #pragma unroll
                for (int j=0;j<8;j++) acc[i][j] += ar[i]*br[j];
        }
        if (t+1 < T){
            int q = p ^ 1;
            As[q][colA+0][rowA] = av2.x; As[q][colA+1][rowA] = av2.y;
            As[q][colA+2][rowA] = av2.z; As[q][colA+3][rowA] = av2.w;
            *(float4*)&Bs[q][rowB][colB] = bv2;
            __syncthreads();
            p = q;
        }
    }

    #pragma unroll
    for (int i = 0; i < 8; i++){
        int row = bm*128 + tr + i;
        if (row >= M) break;
        #pragma unroll
        for (int j = 0; j < 8; j += 4){
            int col = bn*128 + tc + j;
            float b0 = bias ? bias[col+0] : 0.f;
            float b1 = bias ? bias[col+1] : 0.f;
            float b2 = bias ? bias[col+2] : 0.f;
            float b3 = bias ? bias[col+3] : 0.f;
            float4 o;
            o.x = acc[i][j+0] + b0;
            o.y = acc[i][j+1] + b1;
            o.z = acc[i][j+2] + b2;
            o.w = acc[i][j+3] + b3;
            if (mode == 1){
                o.x = fmaxf(o.x,0.f); o.y = fmaxf(o.y,0.f);
                o.z = fmaxf(o.z,0.f); o.w = fmaxf(o.w,0.f);
                *(float4*)&C[(size_t)row*ldc + col] = o;
            } else if (mode == 2){
                bool has = g_cnts[row] > 0.f;
                float4 sg = *(const float4*)&g_seg[(size_t)row*128 + col];
                float s0 = has ? fmaxf(sg.x, 0.f) : 0.f;
                float s1 = has ? fmaxf(sg.y, 0.f) : 0.f;
                float s2 = has ? fmaxf(sg.z, 0.f) : 0.f;
                float s3 = has ? fmaxf(sg.w, 0.f) : 0.f;
                float4 w;
                w.x = s0 / (1.f + __expf(-o.x));
                w.y = s1 / (1.f + __expf(-o.y));
                w.z = s2 / (1.f + __expf(-o.z));
                w.w = s3 / (1.f + __expf(-o.w));
                *(float4*)&C[(size_t)row*ldc + 128 + col] = w;
            } else {
                *(float4*)&C[(size_t)row*ldc + col] = o;
            }
        }
    }
}

// ---------------- tensor-core attention: 32 edges = 128 (e,h) rows per iter ----------------
// dyn smem: As[128][68] u32 | B1[64][72] u32 | B2[64][40] u32 | v_s[32][128] f32 | s_s[32] | sa1[64] | sa2[32]
#define ATT_SMEM ((128*68 + 64*72 + 64*40)*4 + 32*128*4 + 32*4 + 64*4 + 32*4)
__global__ __launch_bounds__(256) void attention_tc(
        const int* __restrict__ src, const int* __restrict__ dst,
        const float* __restrict__ A1, const float* __restrict__ a1,
        const float* __restrict__ A2, const float* __restrict__ a2,
        int E){
    extern __shared__ unsigned sm[];
    unsigned* As = sm;                        // [128][68]
    unsigned* B1 = sm + 128*68;               // [64][72]
    unsigned* B2 = B1 + 64*72;                // [64][40]
    float*   v_s = (float*)(B2 + 64*40);      // [32][128]
    int*     s_s = (int*)(v_s + 32*128);      // [32]
    float*   sa1 = (float*)(s_s + 32);        // [64]
    float*   sa2 = sa1 + 64;                  // [32]

    int t = threadIdx.x, lane = t & 31, w = t >> 5;
    int grp = lane >> 2, tig = lane & 3;

    for (int i = t; i < 4096; i += 256){ int o = i >> 6, c = i & 63; B1[c*72 + o] = f2tf(A1[i]); }
    for (int i = t; i < 2048; i += 256){ int o = i >> 6, c = i & 63; B2[c*40 + o] = f2tf(A2[i]); }
    if (t < 64) sa1[t] = a1[t];
    if (t < 32) sa2[t] = a2[t];

    int el = t >> 3, sub = t & 7;

    for (long long e0 = (long long)blockIdx.x*32; e0 < E; e0 += (long long)gridDim.x*32){
        long long e = e0 + el;
        bool ok = (e < E);
        long long ec = ok ? e : (E-1);
        int s = src[ec], d = dst[ec];
        if (sub == 0) s_s[el] = ok ? s : -1;

        // gather A-tile: row = el*4+h, col c: c<32 -> q[c*4+h], else pe[(c-32)*4+h]
        const float* qrow  = g_qv + (size_t)s*256;
        const float* perow = g_PP + (size_t)ec*PPW + 768;
        #pragma unroll
        for (int f = 0; f < 8; f++){
            int j = sub*32 + f*4;
            float4 v = (j < 128) ? *(const float4*)(qrow + j)
                                 : *(const float4*)(perow + j - 128);
            int c = sub*8 + f;   // uniform: j<128 -> j>>2; else 32+(j-128)>>2
            As[(el*4+0)*68 + c] = f2tf(v.x);
            As[(el*4+1)*68 + c] = f2tf(v.y);
            As[(el*4+2)*68 + c] = f2tf(v.z);
            As[(el*4+3)*68 + c] = f2tf(v.w);
        }
        // v tile
        const float* vrow = g_qv + (size_t)d*256 + 128;
        #pragma unroll
        for (int f = 0; f < 4; f++){
            int j = sub*16 + f*4;
            *(float4*)(v_s + el*128 + j) = *(const float4*)(vrow + j);
        }
        __syncthreads();

        // layer1: [128,64] @ [64,64]
        float acc1[8][4];
        #pragma unroll
        for (int nt=0; nt<8; nt++)
            #pragma unroll
            for (int r=0; r<4; r++) acc1[nt][r] = 0.f;

        int rb = w*16 + grp;
        #pragma unroll
        for (int ks = 0; ks < 8; ks++){
            int kc = ks*8 + tig;
            unsigned a0 = As[rb*68 + kc];
            unsigned a1r = As[(rb+8)*68 + kc];
            unsigned a2r = As[rb*68 + kc+4];
            unsigned a3 = As[(rb+8)*68 + kc+4];
            #pragma unroll
            for (int nt = 0; nt < 8; nt++){
                int cb = nt*8 + grp;
                unsigned b0 = B1[(ks*8+tig)*72 + cb];
                unsigned b1v = B1[(ks*8+tig+4)*72 + cb];
                MMA_TF32(acc1[nt], a0,a1r,a2r,a3, b0,b1v);
            }
        }
        __syncthreads();

        // H1 = relu(acc1 + a1) -> back into As
        #pragma unroll
        for (int nt = 0; nt < 8; nt++){
            int col = nt*8 + tig*2;
            float b0 = sa1[col], b1v = sa1[col+1];
            As[rb*68 + col]       = f2tf(fmaxf(acc1[nt][0]+b0, 0.f));
            As[rb*68 + col+1]     = f2tf(fmaxf(acc1[nt][1]+b1v, 0.f));
            As[(rb+8)*68 + col]   = f2tf(fmaxf(acc1[nt][2]+b0, 0.f));
            As[(rb+8)*68 + col+1] = f2tf(fmaxf(acc1[nt][3]+b1v, 0.f));
        }
        __syncthreads();

        // layer2: [128,64] @ [64,32]
        float acc2[4][4];
        #pragma unroll
        for (int nt=0; nt<4; nt++)
            #pragma unroll
            for (int r=0; r<4; r++) acc2[nt][r] = 0.f;

        #pragma unroll
        for (int ks = 0; ks < 8; ks++){
            int kc = ks*8 + tig;
            unsigned a0 = As[rb*68 + kc];
            unsigned a1r = As[(rb+8)*68 + kc];
            unsigned a2r = As[rb*68 + kc+4];
            unsigned a3 = As[(rb+8)*68 + kc+4];
            #pragma unroll
            for (int nt = 0; nt < 4; nt++){
                int cb = nt*8 + grp;
                unsigned b0 = B2[(ks*8+tig)*40 + cb];
                unsigned b1v = B2[(ks*8+tig+4)*40 + cb];
                MMA_TF32(acc2[nt], a0,a1r,a2r,a3, b0,b1v);
            }
        }

        // add bias, softmax over 32 cols per row (rows rb, rb+8)
        #pragma unroll
        for (int nt = 0; nt < 4; nt++){
            int col = nt*8 + tig*2;
            acc2[nt][0] += sa2[col]; acc2[nt][1] += sa2[col+1];
            acc2[nt][2] += sa2[col]; acc2[nt][3] += sa2[col+1];
        }
        float mA = -1e30f, mB = -1e30f;
        #pragma unroll
        for (int nt = 0; nt < 4; nt++){
            mA = fmaxf(mA, fmaxf(acc2[nt][0], acc2[nt][1]));
            mB = fmaxf(mB, fmaxf(acc2[nt][2], acc2[nt][3]));
        }
        mA = fmaxf(mA, __shfl_xor_sync(0xffffffffu, mA, 1));
        mA = fmaxf(mA, __shfl_xor_sync(0xffffffffu, mA, 2));
        mB = fmaxf(mB, __shfl_xor_sync(0xffffffffu, mB, 1));
        mB = fmaxf(mB, __shfl_xor_sync(0xffffffffu, mB, 2));
        float exv[4][4];
        float sA = 0.f, sB = 0.f;
        #pragma unroll
        for (int nt = 0; nt < 4; nt++){
            exv[nt][0] = __expf(acc2[nt][0] - mA);
            exv[nt][1] = __expf(acc2[nt][1] - mA);
            exv[nt][2] = __expf(acc2[nt][2] - mB);
            exv[nt][3] = __expf(acc2[nt][3] - mB);
            sA += exv[nt][0] + exv[nt][1];
            sB += exv[nt][2] + exv[nt][3];
        }
        sA += __shfl_xor_sync(0xffffffffu, sA, 1);
        sA += __shfl_xor_sync(0xffffffffu, sA, 2);
        sB += __shfl_xor_sync(0xffffffffu, sB, 1);
        sB += __shfl_xor_sync(0xffffffffu, sB, 2);
        float rA = 1.f / sA, rBv = 1.f / sB;

        int elA = rb >> 2,     hA = rb & 3;
        int elB = (rb+8) >> 2, hB = (rb+8) & 3;
        int srcA = s_s[elA], srcB = s_s[elB];
        #pragma unroll
        for (int nt = 0; nt < 4; nt++){
            int col = nt*8 + tig*2;
            if (srcA >= 0){
                float vA0 = exv[nt][0]*rA * v_s[elA*128 + col*4 + hA];
                float vA1 = exv[nt][1]*rA * v_s[elA*128 + (col+1)*4 + hA];
                atomicMaxF(&g_seg[(size_t)srcA*128 + col*4 + hA], vA0);
                atomicMaxF(&g_seg[(size_t)srcA*128 + (col+1)*4 + hA], vA1);
            }
            if (srcB >= 0){
                float vB0 = exv[nt][2]*rBv * v_s[elB*128 + col*4 + hB];
                float vB1 = exv[nt][3]*rBv * v_s[elB*128 + (col+1)*4 + hB];
                atomicMaxF(&g_seg[(size_t)srcB*128 + col*4 + hB], vB0);
                atomicMaxF(&g_seg[(size_t)srcB*128 + (col+1)*4 + hB], vB1);
            }
        }
        __syncthreads();
    }
}

// ---------------- node-side glue ----------------
__global__ void build_twin_in(const float* __restrict__ x, int N){
    int i = blockIdx.x*blockDim.x + threadIdx.x;
    if (i >= N*128) return;
    int n = i >> 7, c = i & 127;
    g_twin_in[(size_t)n*256 + c]       = g_subj[i] / fmaxf(g_cnts[n], 1.f);
    g_twin_in[(size_t)n*256 + 128 + c] = g_obj[i]  / fmaxf(g_cntd[n], 1.f);
    g_xcat[(size_t)n*256 + c] = x[i];
}

// ---------------- final LayerNorm ----------------
__global__ __launch_bounds__(256) void ln_final(
        const float* __restrict__ gn, const float* __restrict__ bn,
        float* __restrict__ out_x, int N){
    int n = blockIdx.x * 8 + (threadIdx.x >> 5);
    if (n >= N) return;
    int lane = threadIdx.x & 31;
    const float* row = g_ptmp + (size_t)n*128;
    float4 v = *(const float4*)&row[lane*4];
    float s  = v.x + v.y + v.z + v.w;
    float ss = v.x*v.x + v.y*v.y + v.z*v.z + v.w*v.w;
    #pragma unroll
    for (int off = 16; off; off >>= 1){
        s  += __shfl_xor_sync(0xffffffffu, s,  off);
        ss += __shfl_xor_sync(0xffffffffu, ss, off);
    }
    float mean = s * (1.f/128.f);
    float var  = ss * (1.f/128.f) - mean*mean;
    float rstd = rsqrtf(var + 1e-5f);
    float vv[4] = {v.x, v.y, v.z, v.w};
    #pragma unroll
    for (int q = 0; q < 4; q++){
        int c = lane*4 + q;
        out_x[(size_t)n*128 + c] = (vv[q] - mean) * rstd * gn[c] + bn[c];
    }
}

// ---------------- host ----------------
extern "C" void kernel_launch(void* const* d_in, const int* in_sizes, int n_in,
                              void* d_out, int out_size){
    const float* x    = (const float*)d_in[0];
    const float* ef   = (const float*)d_in[1];
    const int*   eidx = (const int*)  d_in[2];
    const float* Wg1  = (const float*)d_in[3];
    const float* bg1  = (const float*)d_in[4];
    const float* Wg2  = (const float*)d_in[5];
    const float* bg2  = (const float*)d_in[6];
    const float* We1  = (const float*)d_in[7];
    const float* be1  = (const float*)d_in[8];
    const float* We2  = (const float*)d_in[9];
    const float* be2  = (const float*)d_in[10];
    const float* ge   = (const float*)d_in[11];
    const float* beta_e=(const float*)d_in[12];
    const float* Wq   = (const float*)d_in[13];
    const float* bq   = (const float*)d_in[14];
    const float* Wpe  = (const float*)d_in[15];
    const float* bpe  = (const float*)d_in[16];
    const float* Wv   = (const float*)d_in[17];
    const float* bv   = (const float*)d_in[18];
    const float* A1   = (const float*)d_in[19];
    const float* a1   = (const float*)d_in[20];
    const float* A2   = (const float*)d_in[21];
    const float* a2   = (const float*)d_in[22];
    const float* Wt   = (const float*)d_in[23];
    const float* bt   = (const float*)d_in[24];
    const float* Wp1  = (const float*)d_in[25];
    const float* bp1  = (const float*)d_in[26];
    const float* Wp2  = (const float*)d_in[27];
    const float* bp2  = (const float*)d_in[28];
    const float* gn   = (const float*)d_in[29];
    const float* bn   = (const float*)d_in[30];

    int N = in_sizes[0] / 128;
    int E = in_sizes[2] / 2;
    const int* src = eidx;
    const int* dst = eidx + E;

    float* out_x = (float*)d_out;                        // [N,128]
    float* out_e = (float*)d_out + (size_t)N * 128;      // [E,128]

    float *pPP, *pXX, *pQV, *pTIN, *pXCAT, *pPH, *pPTMP;
    float *pBpE, *pBpN, *pBias, *pWqv, *pbqv;
    cudaGetSymbolAddress((void**)&pPP,   g_PP);
    cudaGetSymbolAddress((void**)&pXX,   g_XX);
    cudaGetSymbolAddress((void**)&pQV,   g_qv);
    cudaGetSymbolAddress((void**)&pTIN,  g_twin_in);
    cudaGetSymbolAddress((void**)&pXCAT, g_xcat);
    cudaGetSymbolAddress((void**)&pPH,   g_ph);
    cudaGetSymbolAddress((void**)&pPTMP, g_ptmp);
    cudaGetSymbolAddress((void**)&pBpE,  g_BpE);
    cudaGetSymbolAddress((void**)&pBpN,  g_BpN);
    cudaGetSymbolAddress((void**)&pBias, g_biasPP);
    cudaGetSymbolAddress((void**)&pWqv,  g_Wqv);
    cudaGetSymbolAddress((void**)&pbqv,  g_bqv);

    cudaFuncSetAttribute(attention_tc, cudaFuncAttributeMaxDynamicSharedMemorySize, ATT_SMEM);

    // 1) init state
    init_kernel<<<2048, 256>>>(N);
    // 2) repack weights
    repack_We1<<<(128*PPW + 255)/256, 256>>>(We1, Wpe, Wg1);
    repack_BpN_bias<<<(128*768 + 255)/256, 256>>>(We1, bpe, bg1);
    repack_qv<<<(128*256 + 255)/256, 256>>>(Wq, bq, Wv, bv);
    // 3) hash insert + degree counts
    hash_insert<<<(E + 255)/256, 256>>>(src, dst, E, N);
    // 4) reverse lookup
    rev_lookup<<<(E + 255)/256, 256>>>(src, dst, E, N);
    // 5) node part of nn_edge layer1: XX = x @ BpN   [N,768] (fp32)
    { dim3 g(768/128, (N+127)/128); sgemm128<<<g,256>>>(x, pBpN, 0, pXX, N, 768, 128, 768, 0); }
    // 6) big edge GEMM (TF32) with fused gate epilogue on bn=7
    { dim3 g(PPW/128, (E+127)/128);
      tgemm_pp<<<g,256>>>(ef, pBpE, pBias, pPP, E, PPW, 128, 7, Wg2, bg2); }
    // 7) fused: build_h1 + h1@We2+be2 + LN + subj/obj scatter -> out_e
    edge_mlp2_ln<<<(E + 127)/128, 256>>>(src, dst, We2, be1, be2, ge, beta_e, out_e, E);
    // 8) fused q|v projection [N,256]
    { dim3 g(2, (N+127)/128); sgemm128<<<g,256>>>(x, pWqv, pbqv, pQV, N, 256, 128, 256, 0); }
    // 9) tensor-core attention + scatter-max
    { int grid = (E + 32*2 - 1) / (32*2); if (grid > 5000) grid = 5000;
      attention_tc<<<5000, 256, ATT_SMEM>>>(src, dst, A1, a1, A2, a2, E); }
    // 10) twin input (segment means) + xcat[:,0:128] = x
    build_twin_in<<<(N*128 + 255)/256, 256>>>(x, N);
    // 11) twin GEMM with fused xcat epilogue -> xcat[:,128:256]
    { dim3 g(1, (N+127)/128); sgemm128<<<g,256>>>(pTIN, Wt, bt, pXCAT, N, 128, 256, 256, 2); }
    // 12) ph = relu(xcat @ Wp1 + bp1)
    { dim3 g(2, (N+127)/128); sgemm128<<<g,256>>>(pXCAT, Wp1, bp1, pPH, N, 256, 256, 256, 1); }
    // 13) ptmp = ph @ Wp2 + bp2
    { dim3 g(1, (N+127)/128); sgemm128<<<g,256>>>(pPH, Wp2, bp2, pPTMP, N, 128, 256, 128, 0); }
    // 14) final LN -> out_x
    ln_final<<<(N + 7)/8, 256>>>(gn, bn, out_x, N);
}